// round 4
// baseline (speedup 1.0000x reference)
#include <cuda_runtime.h>
#include <math.h>

#define NN 50000
#define EE 800000
#define CC 64
#define LDA 68          // padded leading dim for transposed activation tiles
#define NTILES_E (EE/64)  // 12500 exact

// -------- device scratch (sanctioned workaround for no-alloc rule) --------
__device__ float g_v[NN*CC];
__device__ float g_asrc[NN*CC];
__device__ float g_adst[NN*CC];
__device__ float g_sum[NN*CC];
__device__ float g_accum[NN*CC];
__device__ float g_delta[EE*CC];   // 204.8 MB
__device__ float g_eval[EE*CC];    // 204.8 MB  (exp(logit))

// ---------------- 64x64x64 register-tiled GEMM core ----------------
// A^T in smem: sAT[k*LDA + m]  (m = row index, 0..63)
// B   in smem: sW [k*64  + n]  (row-major [k][n])
// 256 threads: tx = tid&15 -> rows tx*4..tx*4+3, ty = tid>>4 -> cols ty*4..ty*4+3
__device__ __forceinline__ void gemm64(const float* __restrict__ sAT,
                                       const float* __restrict__ sW,
                                       int tx, int ty, float acc[4][4]) {
#pragma unroll
  for (int i = 0; i < 4; i++)
#pragma unroll
    for (int j = 0; j < 4; j++) acc[i][j] = 0.f;
#pragma unroll 8
  for (int k = 0; k < 64; k++) {
    float4 a = *(const float4*)(sAT + k*LDA + tx*4);
    float4 b = *(const float4*)(sW  + k*64  + ty*4);
    acc[0][0] = fmaf(a.x, b.x, acc[0][0]);
    acc[0][1] = fmaf(a.x, b.y, acc[0][1]);
    acc[0][2] = fmaf(a.x, b.z, acc[0][2]);
    acc[0][3] = fmaf(a.x, b.w, acc[0][3]);
    acc[1][0] = fmaf(a.y, b.x, acc[1][0]);
    acc[1][1] = fmaf(a.y, b.y, acc[1][1]);
    acc[1][2] = fmaf(a.y, b.z, acc[1][2]);
    acc[1][3] = fmaf(a.y, b.w, acc[1][3]);
    acc[2][0] = fmaf(a.z, b.x, acc[2][0]);
    acc[2][1] = fmaf(a.z, b.y, acc[2][1]);
    acc[2][2] = fmaf(a.z, b.z, acc[2][2]);
    acc[2][3] = fmaf(a.z, b.w, acc[2][3]);
    acc[3][0] = fmaf(a.w, b.x, acc[3][0]);
    acc[3][1] = fmaf(a.w, b.y, acc[3][1]);
    acc[3][2] = fmaf(a.w, b.z, acc[3][2]);
    acc[3][3] = fmaf(a.w, b.w, acc[3][3]);
  }
}

// ---------------- K0: zero accumulators ----------------
__global__ __launch_bounds__(256) void k_zero() {
  int stride = gridDim.x * blockDim.x;
  for (int i = blockIdx.x*blockDim.x + threadIdx.x; i < NN*CC; i += stride) {
    g_sum[i] = 0.f;
    g_accum[i] = 0.f;
  }
}

// ---------------- K1: node projections ----------------
// h = relu(x@W_in + b_in); v = h@W_lin; a_src = h@W_src; a_dst = h@W_dst
__global__ __launch_bounds__(256) void k_node(const float* __restrict__ x,
    const float* __restrict__ Win,  const float* __restrict__ bin,
    const float* __restrict__ Wlin, const float* __restrict__ Wsrc,
    const float* __restrict__ Wdst) {
  __shared__ float sW[4096];
  __shared__ float sB[64];
  __shared__ float sAT[64*LDA];
  int tid = threadIdx.x;
  int tx = tid & 15, ty = tid >> 4;
  int nbase = blockIdx.x * 64;

  // load x tile transposed into sAT[k][n]
#pragma unroll
  for (int t = 0; t < 4; t++) {
    int lin = t*256 + tid;
    int n  = lin >> 4;
    int kk = (lin & 15) << 2;
    float4 v = make_float4(0.f,0.f,0.f,0.f);
    if (nbase + n < NN) v = *(const float4*)(x + (nbase+n)*64 + kk);
    sAT[(kk+0)*LDA + n] = v.x;
    sAT[(kk+1)*LDA + n] = v.y;
    sAT[(kk+2)*LDA + n] = v.z;
    sAT[(kk+3)*LDA + n] = v.w;
  }
#pragma unroll
  for (int t = 0; t < 16; t++) sW[t*256 + tid] = Win[t*256 + tid];
  if (tid < 64) sB[tid] = bin[tid];
  __syncthreads();

  float acc[4][4];
  gemm64(sAT, sW, tx, ty, acc);
  __syncthreads();                       // all done reading sAT (x) and sW

  // write h^T into sAT
#pragma unroll
  for (int j = 0; j < 4; j++)
#pragma unroll
    for (int i = 0; i < 4; i++)
      sAT[(ty*4+j)*LDA + tx*4+i] = fmaxf(acc[i][j] + sB[ty*4+j], 0.f);
  __syncthreads();

#pragma unroll
  for (int m = 0; m < 3; m++) {
    const float* Wm = (m==0) ? Wlin : (m==1) ? Wsrc : Wdst;
    float*       Om = (m==0) ? g_v  : (m==1) ? g_asrc : g_adst;
#pragma unroll
    for (int t = 0; t < 16; t++) sW[t*256 + tid] = Wm[t*256 + tid];
    __syncthreads();
    gemm64(sAT, sW, tx, ty, acc);
#pragma unroll
    for (int i = 0; i < 4; i++) {
      int n = nbase + tx*4 + i;
      if (n < NN)
        *(float4*)(Om + n*64 + ty*4) =
            make_float4(acc[i][0], acc[i][1], acc[i][2], acc[i][3]);
    }
    __syncthreads();   // before next W overwrite
  }
}

// ---------------- K2: fused per-edge MLPs (persistent) ----------------
// per edge: t = relu(rel@Wp1+bp1); delta = t@Wp2+bp2
//           aln = a_dst[dst]-a_src[src]+delta
//           u = relu(aln@Wa1+ba1); logit = u@Wa2+ba2
//           g_delta <- delta; g_eval <- exp(logit); g_sum[dst] += exp(logit)
__global__ __launch_bounds__(256) void k_edge(
    const float* __restrict__ pos, const int* __restrict__ eidx,
    const float* __restrict__ Wp1, const float* __restrict__ bp1,
    const float* __restrict__ Wp2, const float* __restrict__ bp2,
    const float* __restrict__ Wa1, const float* __restrict__ ba1,
    const float* __restrict__ Wa2, const float* __restrict__ ba2) {
  extern __shared__ float sm[];
  float* sWp1 = sm;               // 192
  float* sWp2 = sWp1 + 192;       // 4096
  float* sWa1 = sWp2 + 4096;      // 4096
  float* sWa2 = sWa1 + 4096;      // 4096
  float* sbp1 = sWa2 + 4096;      // 64
  float* sbp2 = sbp1 + 64;        // 64
  float* sba1 = sbp2 + 64;        // 64
  float* sba2 = sba1 + 64;        // 64
  float* sAT  = sba2 + 64;        // 64*LDA
  float* sRel = sAT + 64*LDA;     // 192 (x,y,z planes of 64)
  int*   sSrc = (int*)(sRel + 192);  // 64
  int*   sDst = sSrc + 64;           // 64

  int tid = threadIdx.x;
  int tx = tid & 15, ty = tid >> 4;

  // resident weights
  for (int t = tid; t < 192; t += 256) sWp1[t] = Wp1[t];
#pragma unroll
  for (int t = 0; t < 16; t++) {
    sWp2[t*256 + tid] = Wp2[t*256 + tid];
    sWa1[t*256 + tid] = Wa1[t*256 + tid];
    sWa2[t*256 + tid] = Wa2[t*256 + tid];
  }
  if (tid < 64) {
    sbp1[tid] = bp1[tid]; sbp2[tid] = bp2[tid];
    sba1[tid] = ba1[tid]; sba2[tid] = ba2[tid];
  }
  __syncthreads();

  for (int tile = blockIdx.x; tile < NTILES_E; tile += gridDim.x) {
    int ebase = tile * 64;
    if (tid < 64) {
      sSrc[tid] = eidx[ebase + tid];
      sDst[tid] = eidx[EE + ebase + tid];
    }
    __syncthreads();
    if (tid < 64) {
      int s = sSrc[tid], d = sDst[tid];
      sRel[tid]       = pos[d*3+0] - pos[s*3+0];
      sRel[64 + tid]  = pos[d*3+1] - pos[s*3+1];
      sRel[128 + tid] = pos[d*3+2] - pos[s*3+2];
    }
    __syncthreads();

    // stage P1: t^T into sAT   (K=3, done scalar)
    {
      int h  = tid & 63;
      int e0 = (tid >> 6) * 16;
      float w0 = sWp1[h], w1 = sWp1[64+h], w2 = sWp1[128+h], bb = sbp1[h];
#pragma unroll
      for (int i = 0; i < 16; i++) {
        int e = e0 + i;
        float tv = fmaxf(fmaf(sRel[e], w0,
                         fmaf(sRel[64+e], w1,
                         fmaf(sRel[128+e], w2, bb))), 0.f);
        sAT[h*LDA + e] = tv;
      }
    }
    __syncthreads();

    float acc[4][4];
    // stage P2: delta = t@Wp2 (+bp2 in epilogue)
    gemm64(sAT, sWp2, tx, ty, acc);
    __syncthreads();   // done reading t^T

    // epilogue P2: store delta, build aln^T into sAT
#pragma unroll
    for (int i = 0; i < 4; i++) {
      int e  = tx*4 + i;
      int ge = ebase + e;
      int sn = sSrc[e], dn = sDst[e];
      float4 ad = *(const float4*)(g_adst + dn*64 + ty*4);
      float4 as = *(const float4*)(g_asrc + sn*64 + ty*4);
      float d0 = acc[i][0] + sbp2[ty*4+0];
      float d1 = acc[i][1] + sbp2[ty*4+1];
      float d2 = acc[i][2] + sbp2[ty*4+2];
      float d3 = acc[i][3] + sbp2[ty*4+3];
      *(float4*)(g_delta + ge*64 + ty*4) = make_float4(d0,d1,d2,d3);
      sAT[(ty*4+0)*LDA + e] = ad.x - as.x + d0;
      sAT[(ty*4+1)*LDA + e] = ad.y - as.y + d1;
      sAT[(ty*4+2)*LDA + e] = ad.z - as.z + d2;
      sAT[(ty*4+3)*LDA + e] = ad.w - as.w + d3;
    }
    __syncthreads();

    // stage A1: u = relu(aln@Wa1 + ba1)
    gemm64(sAT, sWa1, tx, ty, acc);
    __syncthreads();
#pragma unroll
    for (int i = 0; i < 4; i++) {
      int e = tx*4 + i;
      sAT[(ty*4+0)*LDA + e] = fmaxf(acc[i][0] + sba1[ty*4+0], 0.f);
      sAT[(ty*4+1)*LDA + e] = fmaxf(acc[i][1] + sba1[ty*4+1], 0.f);
      sAT[(ty*4+2)*LDA + e] = fmaxf(acc[i][2] + sba1[ty*4+2], 0.f);
      sAT[(ty*4+3)*LDA + e] = fmaxf(acc[i][3] + sba1[ty*4+3], 0.f);
    }
    __syncthreads();

    // stage A2: logit = u@Wa2 + ba2 ; exp + segment-sum
    gemm64(sAT, sWa2, tx, ty, acc);
#pragma unroll
    for (int i = 0; i < 4; i++) {
      int e  = tx*4 + i;
      int ge = ebase + e;
      int dn = sDst[e];
      float4 ev;
      ev.x = __expf(acc[i][0] + sba2[ty*4+0]);
      ev.y = __expf(acc[i][1] + sba2[ty*4+1]);
      ev.z = __expf(acc[i][2] + sba2[ty*4+2]);
      ev.w = __expf(acc[i][3] + sba2[ty*4+3]);
      *(float4*)(g_eval + ge*64 + ty*4) = ev;
      atomicAdd(&g_sum[dn*64 + ty*4+0], ev.x);
      atomicAdd(&g_sum[dn*64 + ty*4+1], ev.y);
      atomicAdd(&g_sum[dn*64 + ty*4+2], ev.z);
      atomicAdd(&g_sum[dn*64 + ty*4+3], ev.w);
    }
    __syncthreads();   // protect sSrc/sDst/sAT for next tile
  }
}

// ---------------- K3: normalize + weighted scatter ----------------
__global__ __launch_bounds__(256) void k_scatter(const int* __restrict__ eidx) {
  long long stride = (long long)gridDim.x * blockDim.x;
  const long long total = (long long)EE * 16;  // one float4 lane per thread-item
  for (long long t = (long long)blockIdx.x*blockDim.x + threadIdx.x;
       t < total; t += stride) {
    int e  = (int)(t >> 4);
    int j0 = ((int)t & 15) << 2;
    int sn = eidx[e];
    int dn = eidx[EE + e];
    float4 ev = *(const float4*)(g_eval  + e*64 + j0);
    float4 dl = *(const float4*)(g_delta + e*64 + j0);
    float4 ss = *(const float4*)(g_sum   + dn*64 + j0);
    float4 vv = *(const float4*)(g_v     + sn*64 + j0);
    float c0 = ev.x / (ss.x + 1e-16f) * (vv.x + dl.x);
    float c1 = ev.y / (ss.y + 1e-16f) * (vv.y + dl.y);
    float c2 = ev.z / (ss.z + 1e-16f) * (vv.z + dl.z);
    float c3 = ev.w / (ss.w + 1e-16f) * (vv.w + dl.w);
    atomicAdd(&g_accum[dn*64 + j0+0], c0);
    atomicAdd(&g_accum[dn*64 + j0+1], c1);
    atomicAdd(&g_accum[dn*64 + j0+2], c2);
    atomicAdd(&g_accum[dn*64 + j0+3], c3);
  }
}

// ---------------- K4: out = relu(accum@W_out + b_out) ----------------
__global__ __launch_bounds__(256) void k_out(const float* __restrict__ Wout,
                                             const float* __restrict__ bout,
                                             float* __restrict__ out) {
  __shared__ float sW[4096];
  __shared__ float sB[64];
  __shared__ float sAT[64*LDA];
  int tid = threadIdx.x;
  int tx = tid & 15, ty = tid >> 4;
  int nbase = blockIdx.x * 64;
#pragma unroll
  for (int t = 0; t < 4; t++) {
    int lin = t*256 + tid;
    int n  = lin >> 4;
    int kk = (lin & 15) << 2;
    float4 v = make_float4(0.f,0.f,0.f,0.f);
    if (nbase + n < NN) v = *(const float4*)(g_accum + (nbase+n)*64 + kk);
    sAT[(kk+0)*LDA + n] = v.x;
    sAT[(kk+1)*LDA + n] = v.y;
    sAT[(kk+2)*LDA + n] = v.z;
    sAT[(kk+3)*LDA + n] = v.w;
  }
#pragma unroll
  for (int t = 0; t < 16; t++) sW[t*256 + tid] = Wout[t*256 + tid];
  if (tid < 64) sB[tid] = bout[tid];
  __syncthreads();
  float acc[4][4];
  gemm64(sAT, sW, tx, ty, acc);
#pragma unroll
  for (int i = 0; i < 4; i++) {
    int n = nbase + tx*4 + i;
    if (n < NN) {
      float4 o;
      o.x = fmaxf(acc[i][0] + sB[ty*4+0], 0.f);
      o.y = fmaxf(acc[i][1] + sB[ty*4+1], 0.f);
      o.z = fmaxf(acc[i][2] + sB[ty*4+2], 0.f);
      o.w = fmaxf(acc[i][3] + sB[ty*4+3], 0.f);
      *(float4*)(out + n*64 + ty*4) = o;
    }
  }
}

// ---------------- launch ----------------
extern "C" void kernel_launch(void* const* d_in, const int* in_sizes, int n_in,
                              void* d_out, int out_size) {
  const float* x    = (const float*)d_in[0];
  const float* pos  = (const float*)d_in[1];
  const int*   eidx = (const int*)  d_in[2];
  const float* W_in = (const float*)d_in[3];
  const float* b_in = (const float*)d_in[4];
  const float* W_lin= (const float*)d_in[5];
  const float* W_src= (const float*)d_in[6];
  const float* W_dst= (const float*)d_in[7];
  const float* Wp1  = (const float*)d_in[8];
  const float* bp1  = (const float*)d_in[9];
  const float* Wp2  = (const float*)d_in[10];
  const float* bp2  = (const float*)d_in[11];
  const float* Wa1  = (const float*)d_in[12];
  const float* ba1  = (const float*)d_in[13];
  const float* Wa2  = (const float*)d_in[14];
  const float* ba2  = (const float*)d_in[15];
  const float* W_out= (const float*)d_in[16];
  const float* b_out= (const float*)d_in[17];
  float* out = (float*)d_out;

  const int EDGE_SMEM = 69632;  // 68 KB dynamic smem for k_edge
  cudaFuncSetAttribute(k_edge, cudaFuncAttributeMaxDynamicSharedMemorySize,
                       EDGE_SMEM);

  k_zero<<<2048, 256>>>();
  k_node<<<(NN + 63) / 64, 256>>>(x, W_in, b_in, W_lin, W_src, W_dst);
  k_edge<<<444, 256, EDGE_SMEM>>>(pos, eidx, Wp1, bp1, Wp2, bp2,
                                  Wa1, ba1, Wa2, ba2);
  k_scatter<<<50000, 256>>>(eidx);
  k_out<<<(NN + 63) / 64, 256>>>(W_out, b_out, out);
}

// round 6
// speedup vs baseline: 2.3145x; 2.3145x over previous
#include <cuda_runtime.h>
#include <math.h>
#include <stdint.h>

#define NN 50000
#define EE 800000
#define CC 64
#define LDA 68
#define NT16 50000          // EE/16 warp tiles

// -------- device scratch --------
__device__ float g_v[NN*CC];
__device__ float g_bsrc[NN*CC];    // h@(W_src@Wa1)
__device__ float g_bdst[NN*CC];    // h@(W_dst@Wa1)
__device__ float g_sum[NN*CC];     // softmax denominator
__device__ float g_num[NN*CC];     // unnormalized numerator
__device__ float g_Wsa[CC*CC];     // W_src@Wa1
__device__ float g_Wda[CC*CC];     // W_dst@Wa1
__device__ float g_Wfuse[CC*CC];   // Wp2@Wa1
__device__ float g_cfuse[CC];      // bp2@Wa1 + ba1

// ================= mma.sync tf32 helpers (legacy path, valid on sm_103) ======
__device__ __forceinline__ uint32_t f2tf(float f) {
  uint32_t o;
  asm("cvt.rna.tf32.f32 %0, %1;" : "=r"(o) : "f"(f));
  return o;
}
__device__ __forceinline__ void mma8(float c[4], uint32_t a0, uint32_t a1,
                                     uint32_t a2, uint32_t a3,
                                     uint32_t b0, uint32_t b1) {
  asm volatile(
      "mma.sync.aligned.m16n8k8.row.col.f32.tf32.tf32.f32 "
      "{%0,%1,%2,%3}, {%4,%5,%6,%7}, {%8,%9}, {%0,%1,%2,%3};"
      : "+f"(c[0]), "+f"(c[1]), "+f"(c[2]), "+f"(c[3])
      : "r"(a0), "r"(a1), "r"(a2), "r"(a3), "r"(b0), "r"(b1));
}

// Warp GEMM: [16 x 64] = A[16 x 64] @ B[64 x 64]
// sA: tf32 row-major, stride 76 (conflict-free A-frag loads)
// sB: tf32 [k][n],   stride 72 (conflict-free B-frag loads)
__device__ __forceinline__ void wgemm(const uint32_t* __restrict__ sA,
                                      const uint32_t* __restrict__ sB,
                                      int lane, float acc[8][4]) {
  int r = lane >> 2, q = lane & 3;
#pragma unroll
  for (int n8 = 0; n8 < 8; n8++)
#pragma unroll
    for (int j = 0; j < 4; j++) acc[n8][j] = 0.f;
#pragma unroll
  for (int k8 = 0; k8 < 8; k8++) {
    const uint32_t* ab = sA + k8*8 + q;
    uint32_t a0 = ab[r*76];
    uint32_t a1 = ab[(r+8)*76];
    uint32_t a2 = ab[r*76 + 4];
    uint32_t a3 = ab[(r+8)*76 + 4];
    const uint32_t* bb = sB + (k8*8 + q)*72 + r;
#pragma unroll
    for (int n8 = 0; n8 < 8; n8++) {
      uint32_t b0 = bb[n8*8];
      uint32_t b1 = bb[4*72 + n8*8];
      mma8(acc[n8], a0, a1, a2, a3, b0, b1);
    }
  }
}

// ================= fp32 64x64x64 register-tiled GEMM core =================
__device__ __forceinline__ void gemm64(const float* __restrict__ sAT,
                                       const float* __restrict__ sW,
                                       int tx, int ty, float acc[4][4]) {
#pragma unroll
  for (int i = 0; i < 4; i++)
#pragma unroll
    for (int j = 0; j < 4; j++) acc[i][j] = 0.f;
#pragma unroll 8
  for (int k = 0; k < 64; k++) {
    float4 a = *(const float4*)(sAT + k*LDA + tx*4);
    float4 b = *(const float4*)(sW  + k*64  + ty*4);
    acc[0][0] = fmaf(a.x, b.x, acc[0][0]);
    acc[0][1] = fmaf(a.x, b.y, acc[0][1]);
    acc[0][2] = fmaf(a.x, b.z, acc[0][2]);
    acc[0][3] = fmaf(a.x, b.w, acc[0][3]);
    acc[1][0] = fmaf(a.y, b.x, acc[1][0]);
    acc[1][1] = fmaf(a.y, b.y, acc[1][1]);
    acc[1][2] = fmaf(a.y, b.z, acc[1][2]);
    acc[1][3] = fmaf(a.y, b.w, acc[1][3]);
    acc[2][0] = fmaf(a.z, b.x, acc[2][0]);
    acc[2][1] = fmaf(a.z, b.y, acc[2][1]);
    acc[2][2] = fmaf(a.z, b.z, acc[2][2]);
    acc[2][3] = fmaf(a.z, b.w, acc[2][3]);
    acc[3][0] = fmaf(a.w, b.x, acc[3][0]);
    acc[3][1] = fmaf(a.w, b.y, acc[3][1]);
    acc[3][2] = fmaf(a.w, b.z, acc[3][2]);
    acc[3][3] = fmaf(a.w, b.w, acc[3][3]);
  }
}

// ---------------- K0: zero accumulators ----------------
__global__ __launch_bounds__(256) void k_zero() {
  int stride = gridDim.x * blockDim.x;
  for (int i = blockIdx.x*blockDim.x + threadIdx.x; i < NN*CC; i += stride) {
    g_sum[i] = 0.f;
    g_num[i] = 0.f;
  }
}

// ---------------- KW: weight precompute ----------------
__global__ __launch_bounds__(256) void kw(const float* __restrict__ Wsrc,
    const float* __restrict__ Wdst, const float* __restrict__ Wp2,
    const float* __restrict__ Wa1, const float* __restrict__ bp2,
    const float* __restrict__ ba1) {
  __shared__ float sWa1[4096];
  int tid = threadIdx.x;
#pragma unroll
  for (int t = 0; t < 16; t++) sWa1[t*256 + tid] = Wa1[t*256 + tid];
  __syncthreads();
  const float* A = (blockIdx.x == 0) ? Wsrc : (blockIdx.x == 1) ? Wdst : Wp2;
  float* O = (blockIdx.x == 0) ? g_Wsa : (blockIdx.x == 1) ? g_Wda : g_Wfuse;
  for (int idx = tid; idx < 4096; idx += 256) {
    int k = idx >> 6, n = idx & 63;
    float s = 0.f;
#pragma unroll 16
    for (int m = 0; m < 64; m++) s = fmaf(A[k*64 + m], sWa1[m*64 + n], s);
    O[idx] = s;
  }
  if (blockIdx.x == 2 && tid < 64) {
    float s = ba1[tid];
#pragma unroll 16
    for (int m = 0; m < 64; m++) s = fmaf(bp2[m], sWa1[m*64 + tid], s);
    g_cfuse[tid] = s;
  }
}

// ---------------- K1: node projections (fp32) ----------------
__global__ __launch_bounds__(256) void k_node(const float* __restrict__ x,
    const float* __restrict__ Win, const float* __restrict__ bin,
    const float* __restrict__ Wlin) {
  __shared__ float sW[4096];
  __shared__ float sB[64];
  __shared__ float sAT[64*LDA];
  int tid = threadIdx.x;
  int tx = tid & 15, ty = tid >> 4;
  int nbase = blockIdx.x * 64;

#pragma unroll
  for (int t = 0; t < 4; t++) {
    int lin = t*256 + tid;
    int n  = lin >> 4;
    int kk = (lin & 15) << 2;
    float4 v = make_float4(0.f,0.f,0.f,0.f);
    if (nbase + n < NN) v = *(const float4*)(x + (nbase+n)*64 + kk);
    sAT[(kk+0)*LDA + n] = v.x;
    sAT[(kk+1)*LDA + n] = v.y;
    sAT[(kk+2)*LDA + n] = v.z;
    sAT[(kk+3)*LDA + n] = v.w;
  }
#pragma unroll
  for (int t = 0; t < 16; t++) sW[t*256 + tid] = Win[t*256 + tid];
  if (tid < 64) sB[tid] = bin[tid];
  __syncthreads();

  float acc[4][4];
  gemm64(sAT, sW, tx, ty, acc);
  __syncthreads();

#pragma unroll
  for (int j = 0; j < 4; j++)
#pragma unroll
    for (int i = 0; i < 4; i++)
      sAT[(ty*4+j)*LDA + tx*4+i] = fmaxf(acc[i][j] + sB[ty*4+j], 0.f);
  __syncthreads();

#pragma unroll
  for (int m = 0; m < 3; m++) {
    const float* Wm = (m==0) ? Wlin : (m==1) ? g_Wsa : g_Wda;
    float*       Om = (m==0) ? g_v  : (m==1) ? g_bsrc : g_bdst;
#pragma unroll
    for (int t = 0; t < 16; t++) sW[t*256 + tid] = Wm[t*256 + tid];
    __syncthreads();
    gemm64(sAT, sW, tx, ty, acc);
#pragma unroll
    for (int i = 0; i < 4; i++) {
      int n = nbase + tx*4 + i;
      if (n < NN)
        *(float4*)(Om + n*64 + ty*4) =
            make_float4(acc[i][0], acc[i][1], acc[i][2], acc[i][3]);
    }
    __syncthreads();
  }
}

// ---------------- K2: fused edge kernel (warp-tiled tf32 mma.sync) ----------
// Per 16-edge warp tile:
//   t  = relu(rel@Wp1+bp1)           -> smem A (tf32)
//   D1 = t@Wp2   (delta pre-bias, regs)
//   D2 = t@Wfuse (regs)
//   u  = relu(D2 + bdst[d]-bsrc[s]+cfuse)  -> smem A (tf32)
//   D3 = u@Wa2
//   e = exp(D3+ba2); g_sum[d]+=e; g_num[d]+=e*(v[s]+D1+bp2)
// smem layout (uint32 units):
//   [0,13824)       : 3 weights [64][72] tf32
//   [13824,23552)   : 8 per-warp A tiles [16][76]
//   [23552,23744)   : Wp1 (3x64)
//   [23744,24000)   : bp1|bp2|ba2|cfuse
//   [24000,24256)   : per-warp src/dst (8 x 32)
__global__ void __launch_bounds__(256, 2) k_edge(
    const float* __restrict__ pos, const int* __restrict__ eidx,
    const float* __restrict__ Wp1, const float* __restrict__ bp1,
    const float* __restrict__ Wp2, const float* __restrict__ bp2,
    const float* __restrict__ Wa2, const float* __restrict__ ba2) {
  extern __shared__ uint32_t smu[];
  uint32_t* sWb  = smu;                    // 3 * 4608
  uint32_t* sAall= smu + 13824;            // 8 * 1216
  float* sWp1 = (float*)(smu + 23552);     // 192
  float* sbp1 = sWp1 + 192;                // 64
  float* sbp2 = sbp1 + 64;                 // 64
  float* sba2 = sbp2 + 64;                 // 64
  float* scf  = sba2 + 64;                 // 64
  int*   sIdx = (int*)(scf + 64);          // 8 * 32

  int tid = threadIdx.x;
  int wid = tid >> 5, lane = tid & 31;

  // stage weights as tf32 [k][n], stride 72
  for (int m = 0; m < 3; m++) {
    const float* W = (m == 0) ? Wp2 : (m == 1) ? g_Wfuse : Wa2;
    uint32_t* dst = sWb + m*4608;
    for (int idx = tid; idx < 4096; idx += 256) {
      int k = idx >> 6, n = idx & 63;
      dst[k*72 + n] = f2tf(W[idx]);
    }
  }
  for (int t = tid; t < 192; t += 256) sWp1[t] = Wp1[t];
  if (tid < 64) {
    sbp1[tid] = bp1[tid]; sbp2[tid] = bp2[tid];
    sba2[tid] = ba2[tid]; scf[tid]  = g_cfuse[tid];
  }
  __syncthreads();

  uint32_t* sA = sAall + wid*1216;      // 16 x 76
  int* sS = sIdx + wid*32;
  int* sD = sS + 16;

  const uint32_t* sWd1 = sWb;           // Wp2
  const uint32_t* sWd2 = sWb + 4608;    // Wfuse
  const uint32_t* sWd3 = sWb + 9216;    // Wa2

  int r0l = lane >> 2, q2 = (lane & 3) * 2;

  int gw = blockIdx.x * 8 + wid;
  int nwarp = gridDim.x * 8;
  for (int t = gw; t < NT16; t += nwarp) {
    int eb = t * 16;
    if (lane < 16) sS[lane] = eidx[eb + lane];
    else           sD[lane - 16] = eidx[EE + eb + (lane - 16)];
    __syncwarp();

    // ---- stage t = relu(rel@Wp1+bp1) ----
    {
      int e = lane >> 1, half = lane & 1;
      int s = sS[e], d = sD[e];
      float rx = pos[d*3+0] - pos[s*3+0];
      float ry = pos[d*3+1] - pos[s*3+1];
      float rz = pos[d*3+2] - pos[s*3+2];
      uint32_t* arow = sA + e*76 + half*32;
      const float* w0b = sWp1 + half*32;
#pragma unroll
      for (int j = 0; j < 8; j++) {
        int c = half*32 + j*4;
        float4 w0 = *(const float4*)(sWp1 + c);
        float4 w1 = *(const float4*)(sWp1 + 64 + c);
        float4 w2 = *(const float4*)(sWp1 + 128 + c);
        float4 bb = *(const float4*)(sbp1 + c);
        uint4 tv;
        tv.x = f2tf(fmaxf(fmaf(rx,w0.x,fmaf(ry,w1.x,fmaf(rz,w2.x,bb.x))),0.f));
        tv.y = f2tf(fmaxf(fmaf(rx,w0.y,fmaf(ry,w1.y,fmaf(rz,w2.y,bb.y))),0.f));
        tv.z = f2tf(fmaxf(fmaf(rx,w0.z,fmaf(ry,w1.z,fmaf(rz,w2.z,bb.z))),0.f));
        tv.w = f2tf(fmaxf(fmaf(rx,w0.w,fmaf(ry,w1.w,fmaf(rz,w2.w,bb.w))),0.f));
        *(uint4*)(arow + j*4) = tv;
      }
      (void)w0b;
    }
    __syncwarp();

    float D1[8][4], D2[8][4];
    wgemm(sA, sWd1, lane, D1);
    wgemm(sA, sWd2, lane, D2);

    int dn0 = sD[r0l], sn0 = sS[r0l];
    int dn1 = sD[r0l + 8], sn1 = sS[r0l + 8];
    const float* bd0 = g_bdst + dn0*64;
    const float* bs0 = g_bsrc + sn0*64;
    const float* bd1 = g_bdst + dn1*64;
    const float* bs1 = g_bsrc + sn1*64;

    // ---- epi1: u = relu(D2 + bdst - bsrc + cfuse) -> restage ----
#pragma unroll
    for (int n8 = 0; n8 < 8; n8++) {
      int c = n8*8 + q2;
      float2 B0d = *(const float2*)(bd0 + c);
      float2 B0s = *(const float2*)(bs0 + c);
      float2 B1d = *(const float2*)(bd1 + c);
      float2 B1s = *(const float2*)(bs1 + c);
      float2 cf  = *(const float2*)(scf + c);
      uint2 u0, u1;
      u0.x = f2tf(fmaxf(D2[n8][0] + B0d.x - B0s.x + cf.x, 0.f));
      u0.y = f2tf(fmaxf(D2[n8][1] + B0d.y - B0s.y + cf.y, 0.f));
      u1.x = f2tf(fmaxf(D2[n8][2] + B1d.x - B1s.x + cf.x, 0.f));
      u1.y = f2tf(fmaxf(D2[n8][3] + B1d.y - B1s.y + cf.y, 0.f));
      *(uint2*)(sA + r0l*76 + c)       = u0;
      *(uint2*)(sA + (r0l + 8)*76 + c) = u1;
    }
    __syncwarp();

    float D3[8][4];
    wgemm(sA, sWd3, lane, D3);

    // ---- epi2: e=exp(D3+ba2); atomics ----
    float* gs0 = g_sum + dn0*64; float* gn0 = g_num + dn0*64;
    float* gs1 = g_sum + dn1*64; float* gn1 = g_num + dn1*64;
    const float* gv0 = g_v + sn0*64;
    const float* gv1 = g_v + sn1*64;
#pragma unroll
    for (int n8 = 0; n8 < 8; n8++) {
      int c = n8*8 + q2;
      float2 ba = *(const float2*)(sba2 + c);
      float2 bp = *(const float2*)(sbp2 + c);
      float2 v0 = *(const float2*)(gv0 + c);
      float2 v1 = *(const float2*)(gv1 + c);
      float e00 = __expf(D3[n8][0] + ba.x);
      float e01 = __expf(D3[n8][1] + ba.y);
      float e10 = __expf(D3[n8][2] + ba.x);
      float e11 = __expf(D3[n8][3] + ba.y);
      atomicAdd(gs0 + c,     e00);
      atomicAdd(gs0 + c + 1, e01);
      atomicAdd(gs1 + c,     e10);
      atomicAdd(gs1 + c + 1, e11);
      atomicAdd(gn0 + c,     e00 * (v0.x + D1[n8][0] + bp.x));
      atomicAdd(gn0 + c + 1, e01 * (v0.y + D1[n8][1] + bp.y));
      atomicAdd(gn1 + c,     e10 * (v1.x + D1[n8][2] + bp.x));
      atomicAdd(gn1 + c + 1, e11 * (v1.y + D1[n8][3] + bp.y));
    }
    __syncwarp();
  }
}

// ---------------- K3: out = relu((num/(sum+eps))@W_out + b_out) -------------
__global__ __launch_bounds__(256) void k_final(const float* __restrict__ Wout,
                                               const float* __restrict__ bout,
                                               float* __restrict__ out) {
  __shared__ float sW[4096];
  __shared__ float sB[64];
  __shared__ float sAT[64*LDA];
  int tid = threadIdx.x;
  int tx = tid & 15, ty = tid >> 4;
  int nbase = blockIdx.x * 64;
#pragma unroll
  for (int t = 0; t < 4; t++) {
    int lin = t*256 + tid;
    int n  = lin >> 4;
    int kk = (lin & 15) << 2;
    float4 v = make_float4(0.f,0.f,0.f,0.f);
    if (nbase + n < NN) {
      float4 num = *(const float4*)(g_num + (nbase+n)*64 + kk);
      float4 s   = *(const float4*)(g_sum + (nbase+n)*64 + kk);
      v.x = num.x / (s.x + 1e-16f);
      v.y = num.y / (s.y + 1e-16f);
      v.z = num.z / (s.z + 1e-16f);
      v.w = num.w / (s.w + 1e-16f);
    }
    sAT[(kk+0)*LDA + n] = v.x;
    sAT[(kk+1)*LDA + n] = v.y;
    sAT[(kk+2)*LDA + n] = v.z;
    sAT[(kk+3)*LDA + n] = v.w;
  }
#pragma unroll
  for (int t = 0; t < 16; t++) sW[t*256 + tid] = Wout[t*256 + tid];
  if (tid < 64) sB[tid] = bout[tid];
  __syncthreads();
  float acc[4][4];
  gemm64(sAT, sW, tx, ty, acc);
#pragma unroll
  for (int i = 0; i < 4; i++) {
    int n = nbase + tx*4 + i;
    if (n < NN) {
      float4 o;
      o.x = fmaxf(acc[i][0] + sB[ty*4+0], 0.f);
      o.y = fmaxf(acc[i][1] + sB[ty*4+1], 0.f);
      o.z = fmaxf(acc[i][2] + sB[ty*4+2], 0.f);
      o.w = fmaxf(acc[i][3] + sB[ty*4+3], 0.f);
      *(float4*)(out + n*64 + ty*4) = o;
    }
  }
}

// ---------------- launch ----------------
extern "C" void kernel_launch(void* const* d_in, const int* in_sizes, int n_in,
                              void* d_out, int out_size) {
  const float* x    = (const float*)d_in[0];
  const float* pos  = (const float*)d_in[1];
  const int*   eidx = (const int*)  d_in[2];
  const float* W_in = (const float*)d_in[3];
  const float* b_in = (const float*)d_in[4];
  const float* W_lin= (const float*)d_in[5];
  const float* W_src= (const float*)d_in[6];
  const float* W_dst= (const float*)d_in[7];
  const float* Wp1  = (const float*)d_in[8];
  const float* bp1  = (const float*)d_in[9];
  const float* Wp2  = (const float*)d_in[10];
  const float* bp2  = (const float*)d_in[11];
  const float* Wa1  = (const float*)d_in[12];
  const float* ba1  = (const float*)d_in[13];
  const float* Wa2  = (const float*)d_in[14];
  const float* ba2  = (const float*)d_in[15];
  const float* W_out= (const float*)d_in[16];
  const float* b_out= (const float*)d_in[17];
  float* out = (float*)d_out;

  const int EDGE_SMEM = 24256 * 4;   // 97 KB
  cudaFuncSetAttribute(k_edge, cudaFuncAttributeMaxDynamicSharedMemorySize,
                       EDGE_SMEM);

  k_zero<<<1024, 256>>>();
  kw<<<3, 256>>>(W_src, W_dst, Wp2, Wa1, bp2, ba1);
  k_node<<<(NN + 63) / 64, 256>>>(x, W_in, b_in, W_lin);
  k_edge<<<296, 256, EDGE_SMEM>>>(pos, eidx, Wp1, bp1, Wp2, bp2, Wa2, ba2);
  k_final<<<(NN + 63) / 64, 256>>>(W_out, b_out, out);
}

// round 7
// speedup vs baseline: 2.7223x; 1.1762x over previous
#include <cuda_runtime.h>
#include <math.h>
#include <stdint.h>

#define NN 50000
#define EE 800000
#define CC 64
#define LDA 68
#define NT16 50000          // EE/16 warp tiles

// -------- device scratch --------
__device__ float g_v[NN*CC];
__device__ float g_bsrc[NN*CC];    // h@(W_src@Wa1)
__device__ float g_bdst[NN*CC];    // h@(W_dst@Wa1)
__device__ float g_sum[NN*CC];     // softmax denominator
__device__ float g_num[NN*CC];     // unnormalized numerator
__device__ float g_Wsa[CC*CC];     // W_src@Wa1
__device__ float g_Wda[CC*CC];     // W_dst@Wa1
__device__ float g_Wfuse[CC*CC];   // Wp2@Wa1
__device__ float g_cfuse[CC];      // bp2@Wa1 + ba1

// ================= mma.sync tf32 helpers =================
__device__ __forceinline__ uint32_t f2tf(float f) {
  uint32_t o;
  asm("cvt.rna.tf32.f32 %0, %1;" : "=r"(o) : "f"(f));
  return o;
}
__device__ __forceinline__ void mma8(float c[4], uint32_t a0, uint32_t a1,
                                     uint32_t a2, uint32_t a3,
                                     uint32_t b0, uint32_t b1) {
  asm volatile(
      "mma.sync.aligned.m16n8k8.row.col.f32.tf32.tf32.f32 "
      "{%0,%1,%2,%3}, {%4,%5,%6,%7}, {%8,%9}, {%0,%1,%2,%3};"
      : "+f"(c[0]), "+f"(c[1]), "+f"(c[2]), "+f"(c[3])
      : "r"(a0), "r"(a1), "r"(a2), "r"(a3), "r"(b0), "r"(b1));
}
__device__ __forceinline__ void redv2(float* p, float a, float b) {
  asm volatile("red.global.add.v2.f32 [%0], {%1,%2};"
               :: "l"(p), "f"(a), "f"(b) : "memory");
}

// Dual warp GEMM: D1 = A@B1, D2 = A@B2, A[16x64] in sA (row-major stride 76),
// B in fragment-linear layout: frag(k8,n8) at (k8*8+n8)*64 + lane*2 (uint2).
__device__ __forceinline__ void wgemm2f(const uint32_t* __restrict__ sA,
                                        const uint32_t* __restrict__ sB1,
                                        const uint32_t* __restrict__ sB2,
                                        int lane, float D1[8][4], float D2[8][4]) {
  int r = lane >> 2, q = lane & 3;
#pragma unroll
  for (int n8 = 0; n8 < 8; n8++)
#pragma unroll
    for (int j = 0; j < 4; j++) { D1[n8][j] = 0.f; D2[n8][j] = 0.f; }
#pragma unroll
  for (int k8 = 0; k8 < 8; k8++) {
    const uint32_t* ab = sA + k8*8 + q;
    uint32_t a0 = ab[r*76];
    uint32_t a1 = ab[(r+8)*76];
    uint32_t a2 = ab[r*76 + 4];
    uint32_t a3 = ab[(r+8)*76 + 4];
    const uint32_t* b1 = sB1 + (k8<<9) + (lane<<1);
    const uint32_t* b2 = sB2 + (k8<<9) + (lane<<1);
#pragma unroll
    for (int n8 = 0; n8 < 8; n8++) {
      uint2 w1 = *(const uint2*)(b1 + (n8<<6));
      mma8(D1[n8], a0, a1, a2, a3, w1.x, w1.y);
      uint2 w2 = *(const uint2*)(b2 + (n8<<6));
      mma8(D2[n8], a0, a1, a2, a3, w2.x, w2.y);
    }
  }
}
__device__ __forceinline__ void wgemmf(const uint32_t* __restrict__ sA,
                                       const uint32_t* __restrict__ sB,
                                       int lane, float D[8][4]) {
  int r = lane >> 2, q = lane & 3;
#pragma unroll
  for (int n8 = 0; n8 < 8; n8++)
#pragma unroll
    for (int j = 0; j < 4; j++) D[n8][j] = 0.f;
#pragma unroll
  for (int k8 = 0; k8 < 8; k8++) {
    const uint32_t* ab = sA + k8*8 + q;
    uint32_t a0 = ab[r*76];
    uint32_t a1 = ab[(r+8)*76];
    uint32_t a2 = ab[r*76 + 4];
    uint32_t a3 = ab[(r+8)*76 + 4];
    const uint32_t* bb = sB + (k8<<9) + (lane<<1);
#pragma unroll
    for (int n8 = 0; n8 < 8; n8++) {
      uint2 w = *(const uint2*)(bb + (n8<<6));
      mma8(D[n8], a0, a1, a2, a3, w.x, w.y);
    }
  }
}

// ================= fp32 64x64x64 register-tiled GEMM core =================
__device__ __forceinline__ void gemm64(const float* __restrict__ sAT,
                                       const float* __restrict__ sW,
                                       int tx, int ty, float acc[4][4]) {
#pragma unroll
  for (int i = 0; i < 4; i++)
#pragma unroll
    for (int j = 0; j < 4; j++) acc[i][j] = 0.f;
#pragma unroll 8
  for (int k = 0; k < 64; k++) {
    float4 a = *(const float4*)(sAT + k*LDA + tx*4);
    float4 b = *(const float4*)(sW  + k*64  + ty*4);
    acc[0][0] = fmaf(a.x, b.x, acc[0][0]);
    acc[0][1] = fmaf(a.x, b.y, acc[0][1]);
    acc[0][2] = fmaf(a.x, b.z, acc[0][2]);
    acc[0][3] = fmaf(a.x, b.w, acc[0][3]);
    acc[1][0] = fmaf(a.y, b.x, acc[1][0]);
    acc[1][1] = fmaf(a.y, b.y, acc[1][1]);
    acc[1][2] = fmaf(a.y, b.z, acc[1][2]);
    acc[1][3] = fmaf(a.y, b.w, acc[1][3]);
    acc[2][0] = fmaf(a.z, b.x, acc[2][0]);
    acc[2][1] = fmaf(a.z, b.y, acc[2][1]);
    acc[2][2] = fmaf(a.z, b.z, acc[2][2]);
    acc[2][3] = fmaf(a.z, b.w, acc[2][3]);
    acc[3][0] = fmaf(a.w, b.x, acc[3][0]);
    acc[3][1] = fmaf(a.w, b.y, acc[3][1]);
    acc[3][2] = fmaf(a.w, b.z, acc[3][2]);
    acc[3][3] = fmaf(a.w, b.w, acc[3][3]);
  }
}

// ---------------- K0: zero accumulators ----------------
__global__ __launch_bounds__(256) void k_zero() {
  int stride = gridDim.x * blockDim.x;
  for (int i = blockIdx.x*blockDim.x + threadIdx.x; i < NN*CC; i += stride) {
    g_sum[i] = 0.f;
    g_num[i] = 0.f;
  }
}

// ---------------- KW: weight precompute ----------------
__global__ __launch_bounds__(256) void kw(const float* __restrict__ Wsrc,
    const float* __restrict__ Wdst, const float* __restrict__ Wp2,
    const float* __restrict__ Wa1, const float* __restrict__ bp2,
    const float* __restrict__ ba1) {
  __shared__ float sWa1[4096];
  int tid = threadIdx.x;
#pragma unroll
  for (int t = 0; t < 16; t++) sWa1[t*256 + tid] = Wa1[t*256 + tid];
  __syncthreads();
  const float* A = (blockIdx.x == 0) ? Wsrc : (blockIdx.x == 1) ? Wdst : Wp2;
  float* O = (blockIdx.x == 0) ? g_Wsa : (blockIdx.x == 1) ? g_Wda : g_Wfuse;
  for (int idx = tid; idx < 4096; idx += 256) {
    int k = idx >> 6, n = idx & 63;
    float s = 0.f;
#pragma unroll 16
    for (int m = 0; m < 64; m++) s = fmaf(A[k*64 + m], sWa1[m*64 + n], s);
    O[idx] = s;
  }
  if (blockIdx.x == 2 && tid < 64) {
    float s = ba1[tid];
#pragma unroll 16
    for (int m = 0; m < 64; m++) s = fmaf(bp2[m], sWa1[m*64 + tid], s);
    g_cfuse[tid] = s;
  }
}

// ---------------- K1: node projections (fp32) ----------------
__global__ __launch_bounds__(256) void k_node(const float* __restrict__ x,
    const float* __restrict__ Win, const float* __restrict__ bin,
    const float* __restrict__ Wlin) {
  __shared__ float sW[4096];
  __shared__ float sB[64];
  __shared__ float sAT[64*LDA];
  int tid = threadIdx.x;
  int tx = tid & 15, ty = tid >> 4;
  int nbase = blockIdx.x * 64;

#pragma unroll
  for (int t = 0; t < 4; t++) {
    int lin = t*256 + tid;
    int n  = lin >> 4;
    int kk = (lin & 15) << 2;
    float4 v = make_float4(0.f,0.f,0.f,0.f);
    if (nbase + n < NN) v = *(const float4*)(x + (nbase+n)*64 + kk);
    sAT[(kk+0)*LDA + n] = v.x;
    sAT[(kk+1)*LDA + n] = v.y;
    sAT[(kk+2)*LDA + n] = v.z;
    sAT[(kk+3)*LDA + n] = v.w;
  }
#pragma unroll
  for (int t = 0; t < 16; t++) sW[t*256 + tid] = Win[t*256 + tid];
  if (tid < 64) sB[tid] = bin[tid];
  __syncthreads();

  float acc[4][4];
  gemm64(sAT, sW, tx, ty, acc);
  __syncthreads();

#pragma unroll
  for (int j = 0; j < 4; j++)
#pragma unroll
    for (int i = 0; i < 4; i++)
      sAT[(ty*4+j)*LDA + tx*4+i] = fmaxf(acc[i][j] + sB[ty*4+j], 0.f);
  __syncthreads();

#pragma unroll
  for (int m = 0; m < 3; m++) {
    const float* Wm = (m==0) ? Wlin : (m==1) ? g_Wsa : g_Wda;
    float*       Om = (m==0) ? g_v  : (m==1) ? g_bsrc : g_bdst;
#pragma unroll
    for (int t = 0; t < 16; t++) sW[t*256 + tid] = Wm[t*256 + tid];
    __syncthreads();
    gemm64(sAT, sW, tx, ty, acc);
#pragma unroll
    for (int i = 0; i < 4; i++) {
      int n = nbase + tx*4 + i;
      if (n < NN)
        *(float4*)(Om + n*64 + ty*4) =
            make_float4(acc[i][0], acc[i][1], acc[i][2], acc[i][3]);
    }
    __syncthreads();
  }
}

// ---------------- K2: fused edge kernel ----------------
// smem words:
//  [0,12288)      3 weights in frag-linear layout (tf32)
//  [12288,22016)  8 per-warp A tiles [16][76]
//  [22016,26624)  8 per-warp dump tiles [16][36]
//  [26624,26816)  Wp1
//  [26816,27072)  bp1|bp2|ba2|cfuse
//  [27072,27328)  per-warp src/dst (8 x 32)
#define SM_WORDS 27328
__global__ void __launch_bounds__(256, 2) k_edge(
    const float* __restrict__ pos, const int* __restrict__ eidx,
    const float* __restrict__ Wp1, const float* __restrict__ bp1,
    const float* __restrict__ bp2, const float* __restrict__ Wp2,
    const float* __restrict__ Wa2, const float* __restrict__ ba2) {
  extern __shared__ uint32_t smu[];
  uint32_t* sWf  = smu;                    // 3 * 4096
  uint32_t* sAall= smu + 12288;            // 8 * 1216
  float*    sDall= (float*)(smu + 22016);  // 8 * 576
  float* sWp1 = (float*)(smu + 26624);     // 192
  float* sbp1 = sWp1 + 192;                // 64
  float* sbp2 = sbp1 + 64;                 // 64
  float* sba2 = sbp2 + 64;                 // 64
  float* scf  = sba2 + 64;                 // 64
  int*   sIdx = (int*)(scf + 64);          // 8 * 32

  int tid = threadIdx.x;
  int wid = tid >> 5, lane = tid & 31;

  // stage weights into fragment-linear tf32 layout:
  // dst[(k8*8+n8)*64 + lane*2 + t] = W[(k8*8+q+t*4)][n8*8+r],  lane=(r<<2)|q
  for (int m = 0; m < 3; m++) {
    const float* W = (m == 0) ? Wp2 : (m == 1) ? g_Wfuse : Wa2;
    uint32_t* dst = sWf + m*4096;
    for (int idx = tid; idx < 4096; idx += 256) {
      int tbit = idx & 1;
      int ln   = (idx & 63) >> 1;
      int kn   = idx >> 6;
      int k8 = kn >> 3, n8 = kn & 7;
      int r = ln >> 2, q = ln & 3;
      dst[idx] = f2tf(W[(k8*8 + q + tbit*4)*64 + n8*8 + r]);
    }
  }
  for (int t = tid; t < 192; t += 256) sWp1[t] = Wp1[t];
  if (tid < 64) {
    sbp1[tid] = bp1[tid]; sbp2[tid] = bp2[tid];
    sba2[tid] = ba2[tid]; scf[tid]  = g_cfuse[tid];
  }
  __syncthreads();

  uint32_t* sA = sAall + wid*1216;      // 16 x 76 (t / u / D1 dump)
  float*    sD = sDall + wid*576;       // 16 x 36 (D2 / D3 half dumps)
  int* sS = sIdx + wid*32;
  int* sDn = sS + 16;

  const uint32_t* sW1 = sWf;            // Wp2
  const uint32_t* sW2 = sWf + 4096;     // Wfuse
  const uint32_t* sW3 = sWf + 8192;     // Wa2

  int r = lane >> 2, q = lane & 3;
  // edge-major epilogue mapping: 8 lanes per edge, 4 edges per group
  int eg = lane >> 3;                   // edge within group of 4
  int c8 = lane & 7;                    // column chunk (x4 floats)

  int gw = blockIdx.x * 8 + wid;
  int nwarp = gridDim.x * 8;
  for (int t = gw; t < NT16; t += nwarp) {
    int eb = t * 16;
    if (lane < 16) sS[lane] = eidx[eb + lane];
    else           sDn[lane - 16] = eidx[EE + eb + (lane - 16)];
    __syncwarp();

    // ---- stage t = relu(rel@Wp1+bp1) into sA ----
    {
      int e = lane >> 1, half = lane & 1;
      int s = sS[e], d = sDn[e];
      float rx = pos[d*3+0] - pos[s*3+0];
      float ry = pos[d*3+1] - pos[s*3+1];
      float rz = pos[d*3+2] - pos[s*3+2];
      uint32_t* arow = sA + e*76 + half*32;
#pragma unroll
      for (int j = 0; j < 8; j++) {
        int c = half*32 + j*4;
        float4 w0 = *(const float4*)(sWp1 + c);
        float4 w1 = *(const float4*)(sWp1 + 64 + c);
        float4 w2 = *(const float4*)(sWp1 + 128 + c);
        float4 bb = *(const float4*)(sbp1 + c);
        uint4 tv;
        tv.x = f2tf(fmaxf(fmaf(rx,w0.x,fmaf(ry,w1.x,fmaf(rz,w2.x,bb.x))),0.f));
        tv.y = f2tf(fmaxf(fmaf(rx,w0.y,fmaf(ry,w1.y,fmaf(rz,w2.y,bb.y))),0.f));
        tv.z = f2tf(fmaxf(fmaf(rx,w0.z,fmaf(ry,w1.z,fmaf(rz,w2.z,bb.z))),0.f));
        tv.w = f2tf(fmaxf(fmaf(rx,w0.w,fmaf(ry,w1.w,fmaf(rz,w2.w,bb.w))),0.f));
        *(uint4*)(arow + j*4) = tv;
      }
    }
    __syncwarp();

    // ---- dual GEMM: D1 = t@Wp2, D2 = t@Wfuse ----
    float D1[8][4], D2[8][4];
    wgemm2f(sA, sW1, sW2, lane, D1, D2);

    // ---- epi1 in two n-halves: u = relu(D2 + bdst - bsrc + cfuse) ----
#pragma unroll
    for (int h = 0; h < 2; h++) {
      // dump D2 half into sD (row-major 16 x 32, stride 36)
#pragma unroll
      for (int n8l = 0; n8l < 4; n8l++) {
        int n8 = h*4 + n8l;
        *(float2*)(sD + r*36 + n8l*8 + q*2) =
            make_float2(D2[n8][0], D2[n8][1]);
        *(float2*)(sD + (r+8)*36 + n8l*8 + q*2) =
            make_float2(D2[n8][2], D2[n8][3]);
      }
      __syncwarp();
#pragma unroll
      for (int s4 = 0; s4 < 4; s4++) {
        int e = s4*4 + eg;
        int dn = sDn[e], sn = sS[e];
        int cg = h*32 + c8*4;
        float4 d2 = *(const float4*)(sD + e*36 + c8*4);
        float4 bd = *(const float4*)(g_bdst + dn*64 + cg);
        float4 bs = *(const float4*)(g_bsrc + sn*64 + cg);
        float4 cf = *(const float4*)(scf + cg);
        uint4 u;
        u.x = f2tf(fmaxf(d2.x + bd.x - bs.x + cf.x, 0.f));
        u.y = f2tf(fmaxf(d2.y + bd.y - bs.y + cf.y, 0.f));
        u.z = f2tf(fmaxf(d2.z + bd.z - bs.z + cf.z, 0.f));
        u.w = f2tf(fmaxf(d2.w + bd.w - bs.w + cf.w, 0.f));
        *(uint4*)(sA + e*76 + cg) = u;
      }
      __syncwarp();
    }

    // ---- D3 = u@Wa2 ----
    float D3[8][4];
    wgemmf(sA, sW3, lane, D3);
    __syncwarp();

    // ---- dump D1 (fp32) into sA row-major (u dead) ----
#pragma unroll
    for (int n8 = 0; n8 < 8; n8++) {
      *(float2*)((float*)sA + r*76 + n8*8 + q*2) =
          make_float2(D1[n8][0], D1[n8][1]);
      *(float2*)((float*)sA + (r+8)*76 + n8*8 + q*2) =
          make_float2(D1[n8][2], D1[n8][3]);
    }

    // ---- epi2 in two n-halves: e=exp(D3+ba2); red to g_sum/g_num ----
#pragma unroll
    for (int h = 0; h < 2; h++) {
#pragma unroll
      for (int n8l = 0; n8l < 4; n8l++) {
        int n8 = h*4 + n8l;
        *(float2*)(sD + r*36 + n8l*8 + q*2) =
            make_float2(D3[n8][0], D3[n8][1]);
        *(float2*)(sD + (r+8)*36 + n8l*8 + q*2) =
            make_float2(D3[n8][2], D3[n8][3]);
      }
      __syncwarp();
#pragma unroll
      for (int s4 = 0; s4 < 4; s4++) {
        int e = s4*4 + eg;
        int dn = sDn[e], sn = sS[e];
        int cg = h*32 + c8*4;
        float4 lg = *(const float4*)(sD + e*36 + c8*4);
        float4 d1 = *(const float4*)((const float*)sA + e*76 + cg);
        float4 vv = *(const float4*)(g_v + sn*64 + cg);
        float4 ba = *(const float4*)(sba2 + cg);
        float4 bp = *(const float4*)(sbp2 + cg);
        float e0 = __expf(lg.x + ba.x);
        float e1 = __expf(lg.y + ba.y);
        float e2 = __expf(lg.z + ba.z);
        float e3 = __expf(lg.w + ba.w);
        redv2(g_sum + dn*64 + cg,     e0, e1);
        redv2(g_sum + dn*64 + cg + 2, e2, e3);
        redv2(g_num + dn*64 + cg,
              e0 * (vv.x + d1.x + bp.x), e1 * (vv.y + d1.y + bp.y));
        redv2(g_num + dn*64 + cg + 2,
              e2 * (vv.z + d1.z + bp.z), e3 * (vv.w + d1.w + bp.w));
      }
      __syncwarp();
    }
  }
}

// ---------------- K3: out = relu((num/(sum+eps))@W_out + b_out) -------------
__global__ __launch_bounds__(256) void k_final(const float* __restrict__ Wout,
                                               const float* __restrict__ bout,
                                               float* __restrict__ out) {
  __shared__ float sW[4096];
  __shared__ float sB[64];
  __shared__ float sAT[64*LDA];
  int tid = threadIdx.x;
  int tx = tid & 15, ty = tid >> 4;
  int nbase = blockIdx.x * 64;
#pragma unroll
  for (int t = 0; t < 4; t++) {
    int lin = t*256 + tid;
    int n  = lin >> 4;
    int kk = (lin & 15) << 2;
    float4 v = make_float4(0.f,0.f,0.f,0.f);
    if (nbase + n < NN) {
      float4 num = *(const float4*)(g_num + (nbase+n)*64 + kk);
      float4 s   = *(const float4*)(g_sum + (nbase+n)*64 + kk);
      v.x = num.x / (s.x + 1e-16f);
      v.y = num.y / (s.y + 1e-16f);
      v.z = num.z / (s.z + 1e-16f);
      v.w = num.w / (s.w + 1e-16f);
    }
    sAT[(kk+0)*LDA + n] = v.x;
    sAT[(kk+1)*LDA + n] = v.y;
    sAT[(kk+2)*LDA + n] = v.z;
    sAT[(kk+3)*LDA + n] = v.w;
  }
#pragma unroll
  for (int t = 0; t < 16; t++) sW[t*256 + tid] = Wout[t*256 + tid];
  if (tid < 64) sB[tid] = bout[tid];
  __syncthreads();
  float acc[4][4];
  gemm64(sAT, sW, tx, ty, acc);
#pragma unroll
  for (int i = 0; i < 4; i++) {
    int n = nbase + tx*4 + i;
    if (n < NN) {
      float4 o;
      o.x = fmaxf(acc[i][0] + sB[ty*4+0], 0.f);
      o.y = fmaxf(acc[i][1] + sB[ty*4+1], 0.f);
      o.z = fmaxf(acc[i][2] + sB[ty*4+2], 0.f);
      o.w = fmaxf(acc[i][3] + sB[ty*4+3], 0.f);
      *(float4*)(out + n*64 + ty*4) = o;
    }
  }
}

// ---------------- launch ----------------
extern "C" void kernel_launch(void* const* d_in, const int* in_sizes, int n_in,
                              void* d_out, int out_size) {
  const float* x    = (const float*)d_in[0];
  const float* pos  = (const float*)d_in[1];
  const int*   eidx = (const int*)  d_in[2];
  const float* W_in = (const float*)d_in[3];
  const float* b_in = (const float*)d_in[4];
  const float* W_lin= (const float*)d_in[5];
  const float* W_src= (const float*)d_in[6];
  const float* W_dst= (const float*)d_in[7];
  const float* Wp1  = (const float*)d_in[8];
  const float* bp1  = (const float*)d_in[9];
  const float* Wp2  = (const float*)d_in[10];
  const float* bp2  = (const float*)d_in[11];
  const float* Wa1  = (const float*)d_in[12];
  const float* ba1  = (const float*)d_in[13];
  const float* Wa2  = (const float*)d_in[14];
  const float* ba2  = (const float*)d_in[15];
  const float* W_out= (const float*)d_in[16];
  const float* b_out= (const float*)d_in[17];
  float* out = (float*)d_out;

  const int EDGE_SMEM = SM_WORDS * 4;   // 109312 B
  cudaFuncSetAttribute(k_edge, cudaFuncAttributeMaxDynamicSharedMemorySize,
                       EDGE_SMEM);

  k_zero<<<1024, 256>>>();
  kw<<<3, 256>>>(W_src, W_dst, Wp2, Wa1, bp2, ba1);
  k_node<<<(NN + 63) / 64, 256>>>(x, W_in, b_in, W_lin);
  k_edge<<<296, 256, EDGE_SMEM>>>(pos, eidx, Wp1, bp1, bp2, Wp2, Wa2, ba2);
  k_final<<<(NN + 63) / 64, 256>>>(W_out, b_out, out);
}

// round 8
// speedup vs baseline: 3.3186x; 1.2191x over previous
#include <cuda_runtime.h>
#include <math.h>
#include <stdint.h>

#define NN 50000
#define EE 800000
#define CC 64
#define LDA 68
#define NT16 50000          // EE/16 warp tiles

// -------- device scratch --------
__device__ float g_v[NN*CC];
__device__ float g_bsrc[NN*CC];    // h@(W_src@Wa1)
__device__ float g_bdst[NN*CC];    // h@(W_dst@Wa1)
__device__ float g_sum[NN*CC];     // softmax denominator
__device__ float g_num[NN*CC];     // unnormalized numerator
__device__ float g_Wsa[CC*CC];     // W_src@Wa1
__device__ float g_Wda[CC*CC];     // W_dst@Wa1
__device__ float g_Wfuse[CC*CC];   // Wp2@Wa1
__device__ float g_cfuse[CC];      // bp2@Wa1 + ba1

// ================= mma.sync tf32 helpers =================
__device__ __forceinline__ uint32_t f2tf(float f) {
  uint32_t o;
  asm("cvt.rna.tf32.f32 %0, %1;" : "=r"(o) : "f"(f));
  return o;
}
__device__ __forceinline__ void mma8(float c[4], uint32_t a0, uint32_t a1,
                                     uint32_t a2, uint32_t a3,
                                     uint32_t b0, uint32_t b1) {
  asm volatile(
      "mma.sync.aligned.m16n8k8.row.col.f32.tf32.tf32.f32 "
      "{%0,%1,%2,%3}, {%4,%5,%6,%7}, {%8,%9}, {%0,%1,%2,%3};"
      : "+f"(c[0]), "+f"(c[1]), "+f"(c[2]), "+f"(c[3])
      : "r"(a0), "r"(a1), "r"(a2), "r"(a3), "r"(b0), "r"(b1));
}
__device__ __forceinline__ void redv4(float* p, float a, float b, float c, float d) {
  asm volatile("red.global.add.v4.f32 [%0], {%1,%2,%3,%4};"
               :: "l"(p), "f"(a), "f"(b), "f"(c), "f"(d) : "memory");
}

// Dual warp GEMM with A in registers: D1 = A@B1, D2 = A@B2.
// B in fragment-linear layout: frag(k8,n8) at (k8*8+n8)*64 + lane*2 (uint2).
__device__ __forceinline__ void wgemm2r(const uint32_t A[8][4],
                                        const uint32_t* __restrict__ sB1,
                                        const uint32_t* __restrict__ sB2,
                                        int lane, float D1[8][4], float D2[8][4]) {
#pragma unroll
  for (int n8 = 0; n8 < 8; n8++)
#pragma unroll
    for (int j = 0; j < 4; j++) { D1[n8][j] = 0.f; D2[n8][j] = 0.f; }
#pragma unroll
  for (int k8 = 0; k8 < 8; k8++) {
    const uint32_t* b1 = sB1 + (k8<<9) + (lane<<1);
    const uint32_t* b2 = sB2 + (k8<<9) + (lane<<1);
#pragma unroll
    for (int n8 = 0; n8 < 8; n8++) {
      uint2 w1 = *(const uint2*)(b1 + (n8<<6));
      mma8(D1[n8], A[k8][0], A[k8][1], A[k8][2], A[k8][3], w1.x, w1.y);
      uint2 w2 = *(const uint2*)(b2 + (n8<<6));
      mma8(D2[n8], A[k8][0], A[k8][1], A[k8][2], A[k8][3], w2.x, w2.y);
    }
  }
}
__device__ __forceinline__ void wgemmr(const uint32_t A[8][4],
                                       const uint32_t* __restrict__ sB,
                                       int lane, float D[8][4]) {
#pragma unroll
  for (int n8 = 0; n8 < 8; n8++)
#pragma unroll
    for (int j = 0; j < 4; j++) D[n8][j] = 0.f;
#pragma unroll
  for (int k8 = 0; k8 < 8; k8++) {
    const uint32_t* bb = sB + (k8<<9) + (lane<<1);
#pragma unroll
    for (int n8 = 0; n8 < 8; n8++) {
      uint2 w = *(const uint2*)(bb + (n8<<6));
      mma8(D[n8], A[k8][0], A[k8][1], A[k8][2], A[k8][3], w.x, w.y);
    }
  }
}

// ================= fp32 64x64x64 register-tiled GEMM core =================
__device__ __forceinline__ void gemm64(const float* __restrict__ sAT,
                                       const float* __restrict__ sW,
                                       int tx, int ty, float acc[4][4]) {
#pragma unroll
  for (int i = 0; i < 4; i++)
#pragma unroll
    for (int j = 0; j < 4; j++) acc[i][j] = 0.f;
#pragma unroll 8
  for (int k = 0; k < 64; k++) {
    float4 a = *(const float4*)(sAT + k*LDA + tx*4);
    float4 b = *(const float4*)(sW  + k*64  + ty*4);
    acc[0][0] = fmaf(a.x, b.x, acc[0][0]);
    acc[0][1] = fmaf(a.x, b.y, acc[0][1]);
    acc[0][2] = fmaf(a.x, b.z, acc[0][2]);
    acc[0][3] = fmaf(a.x, b.w, acc[0][3]);
    acc[1][0] = fmaf(a.y, b.x, acc[1][0]);
    acc[1][1] = fmaf(a.y, b.y, acc[1][1]);
    acc[1][2] = fmaf(a.y, b.z, acc[1][2]);
    acc[1][3] = fmaf(a.y, b.w, acc[1][3]);
    acc[2][0] = fmaf(a.z, b.x, acc[2][0]);
    acc[2][1] = fmaf(a.z, b.y, acc[2][1]);
    acc[2][2] = fmaf(a.z, b.z, acc[2][2]);
    acc[2][3] = fmaf(a.z, b.w, acc[2][3]);
    acc[3][0] = fmaf(a.w, b.x, acc[3][0]);
    acc[3][1] = fmaf(a.w, b.y, acc[3][1]);
    acc[3][2] = fmaf(a.w, b.z, acc[3][2]);
    acc[3][3] = fmaf(a.w, b.w, acc[3][3]);
  }
}

// ---------------- KW: weight precompute ----------------
__global__ __launch_bounds__(256) void kw(const float* __restrict__ Wsrc,
    const float* __restrict__ Wdst, const float* __restrict__ Wp2,
    const float* __restrict__ Wa1, const float* __restrict__ bp2,
    const float* __restrict__ ba1) {
  __shared__ float sWa1[4096];
  int tid = threadIdx.x;
#pragma unroll
  for (int t = 0; t < 16; t++) sWa1[t*256 + tid] = Wa1[t*256 + tid];
  __syncthreads();
  const float* A = (blockIdx.x == 0) ? Wsrc : (blockIdx.x == 1) ? Wdst : Wp2;
  float* O = (blockIdx.x == 0) ? g_Wsa : (blockIdx.x == 1) ? g_Wda : g_Wfuse;
  for (int idx = tid; idx < 4096; idx += 256) {
    int k = idx >> 6, n = idx & 63;
    float s = 0.f;
#pragma unroll 16
    for (int m = 0; m < 64; m++) s = fmaf(A[k*64 + m], sWa1[m*64 + n], s);
    O[idx] = s;
  }
  if (blockIdx.x == 2 && tid < 64) {
    float s = ba1[tid];
#pragma unroll 16
    for (int m = 0; m < 64; m++) s = fmaf(bp2[m], sWa1[m*64 + tid], s);
    g_cfuse[tid] = s;
  }
}

// ---------------- K1: node projections + accumulator zeroing ----------------
__global__ __launch_bounds__(256) void k_node(const float* __restrict__ x,
    const float* __restrict__ Win, const float* __restrict__ bin,
    const float* __restrict__ Wlin) {
  __shared__ float sW[4096];
  __shared__ float sB[64];
  __shared__ float sAT[64*LDA];
  int tid = threadIdx.x;
  int tx = tid & 15, ty = tid >> 4;
  int nbase = blockIdx.x * 64;

  // zero g_sum/g_num for this node tile (fused k_zero)
  {
    float4 z = make_float4(0.f,0.f,0.f,0.f);
#pragma unroll
    for (int j = 0; j < 4; j++) {
      int off = tid*16 + j*4;
      int n = nbase + (off >> 6);
      if (n < NN) {
        *(float4*)(g_sum + nbase*64 + off) = z;
        *(float4*)(g_num + nbase*64 + off) = z;
      }
    }
  }

#pragma unroll
  for (int t = 0; t < 4; t++) {
    int lin = t*256 + tid;
    int n  = lin >> 4;
    int kk = (lin & 15) << 2;
    float4 v = make_float4(0.f,0.f,0.f,0.f);
    if (nbase + n < NN) v = *(const float4*)(x + (nbase+n)*64 + kk);
    sAT[(kk+0)*LDA + n] = v.x;
    sAT[(kk+1)*LDA + n] = v.y;
    sAT[(kk+2)*LDA + n] = v.z;
    sAT[(kk+3)*LDA + n] = v.w;
  }
#pragma unroll
  for (int t = 0; t < 16; t++) sW[t*256 + tid] = Win[t*256 + tid];
  if (tid < 64) sB[tid] = bin[tid];
  __syncthreads();

  float acc[4][4];
  gemm64(sAT, sW, tx, ty, acc);
  __syncthreads();

#pragma unroll
  for (int j = 0; j < 4; j++)
#pragma unroll
    for (int i = 0; i < 4; i++)
      sAT[(ty*4+j)*LDA + tx*4+i] = fmaxf(acc[i][j] + sB[ty*4+j], 0.f);
  __syncthreads();

#pragma unroll
  for (int m = 0; m < 3; m++) {
    const float* Wm = (m==0) ? Wlin : (m==1) ? g_Wsa : g_Wda;
    float*       Om = (m==0) ? g_v  : (m==1) ? g_bsrc : g_bdst;
#pragma unroll
    for (int t = 0; t < 16; t++) sW[t*256 + tid] = Wm[t*256 + tid];
    __syncthreads();
    gemm64(sAT, sW, tx, ty, acc);
#pragma unroll
    for (int i = 0; i < 4; i++) {
      int n = nbase + tx*4 + i;
      if (n < NN)
        *(float4*)(Om + n*64 + ty*4) =
            make_float4(acc[i][0], acc[i][1], acc[i][2], acc[i][3]);
    }
    __syncthreads();
  }
}

// ---------------- K2: fused edge kernel ----------------
// smem words:
//  [0,12288)       3 weights frag-linear tf32 (Wp2 | Wfuse | Wa2)
//  [12288,24576)   8 per-warp scratch (1536 each): g[16x72] / epi2 halves 2x[16x40]
//  [24576,24832)   Wp1 packed float4 per col: {w0,w1,w2,bp1}
//  [24832,24896)   bp2
//  [24896,24960)   ba2
//  [24960,25024)   cfuse
//  [25024,25408)   8 per-warp rel (48 each)
//  [25408,25664)   8 per-warp src/dst (32 each)
#define SM_WORDS 25664
__global__ void __launch_bounds__(256, 2) k_edge(
    const float* __restrict__ pos, const int* __restrict__ eidx,
    const float* __restrict__ Wp1, const float* __restrict__ bp1,
    const float* __restrict__ bp2, const float* __restrict__ Wp2,
    const float* __restrict__ Wa2, const float* __restrict__ ba2) {
  extern __shared__ uint32_t smu[];
  uint32_t* sWf   = smu;                    // 12288
  float*    sScr  = (float*)(smu + 12288);  // 12288
  float4*   sWp1p = (float4*)(smu + 24576); // 64 float4
  float* sbp2 = (float*)(smu + 24832);
  float* sba2 = (float*)(smu + 24896);
  float* scf  = (float*)(smu + 24960);
  float* sRelAll = (float*)(smu + 25024);
  int*   sIdxAll = (int*)(smu + 25408);

  int tid = threadIdx.x;
  int wid = tid >> 5, lane = tid & 31;

  // stage weights into fragment-linear tf32 layout:
  // dst[(k8*8+n8)*64 + ln*2 + t] = W[(k8*8+q+t*4)][n8*8+r],  ln=(r<<2)|q
  for (int m = 0; m < 3; m++) {
    const float* W = (m == 0) ? Wp2 : (m == 1) ? g_Wfuse : Wa2;
    uint32_t* dst = sWf + m*4096;
    for (int idx = tid; idx < 4096; idx += 256) {
      int tbit = idx & 1;
      int ln   = (idx & 63) >> 1;
      int kn   = idx >> 6;
      int k8 = kn >> 3, n8 = kn & 7;
      int rr = ln >> 2, qq = ln & 3;
      dst[idx] = f2tf(W[(k8*8 + qq + tbit*4)*64 + n8*8 + rr]);
    }
  }
  if (tid < 64) {
    sWp1p[tid] = make_float4(Wp1[tid], Wp1[64+tid], Wp1[128+tid], bp1[tid]);
    sbp2[tid] = bp2[tid]; sba2[tid] = ba2[tid]; scf[tid] = g_cfuse[tid];
  }
  __syncthreads();

  float* scr = sScr + wid*1536;       // g: 16x72; epi2: [0,640) D1h, [640,1280) D3h
  float* sRel = sRelAll + wid*48;
  int* sS = sIdxAll + wid*32;
  int* sD = sS + 16;

  const uint32_t* sW1 = sWf;            // Wp2
  const uint32_t* sW2 = sWf + 4096;     // Wfuse
  const uint32_t* sW3 = sWf + 8192;     // Wa2

  int r = lane >> 2, q = lane & 3;
  int eg = lane >> 3, c8 = lane & 7;    // edge-major epilogue mapping
  int Slo = (lane & ~3) | (q >> 1);
  int Shi = Slo + 2;
  int odd = q & 1;

  int gw = blockIdx.x * 8 + wid;
  int nwarp = gridDim.x * 8;
  for (int t = gw; t < NT16; t += nwarp) {
    int eb = t * 16;
    if (lane < 16) sS[lane] = eidx[eb + lane];
    else           sD[lane - 16] = eidx[EE + eb + (lane - 16)];
    __syncwarp();
    if (lane < 16) {
      int s = sS[lane], d = sD[lane];
      sRel[lane]      = pos[d*3+0] - pos[s*3+0];
      sRel[16 + lane] = pos[d*3+1] - pos[s*3+1];
      sRel[32 + lane] = pos[d*3+2] - pos[s*3+2];
    }
    __syncwarp();

    // ---- t-fragments directly in registers ----
    float rx0 = sRel[r],     ry0 = sRel[16+r],   rz0 = sRel[32+r];
    float rx1 = sRel[r+8],   ry1 = sRel[16+r+8], rz1 = sRel[32+r+8];
    uint32_t At[8][4];
#pragma unroll
    for (int k8 = 0; k8 < 8; k8++) {
      float4 wA = sWp1p[k8*8 + q];
      float4 wB = sWp1p[k8*8 + q + 4];
      At[k8][0] = f2tf(fmaxf(fmaf(rx0,wA.x,fmaf(ry0,wA.y,fmaf(rz0,wA.z,wA.w))),0.f));
      At[k8][1] = f2tf(fmaxf(fmaf(rx1,wA.x,fmaf(ry1,wA.y,fmaf(rz1,wA.z,wA.w))),0.f));
      At[k8][2] = f2tf(fmaxf(fmaf(rx0,wB.x,fmaf(ry0,wB.y,fmaf(rz0,wB.z,wB.w))),0.f));
      At[k8][3] = f2tf(fmaxf(fmaf(rx1,wB.x,fmaf(ry1,wB.y,fmaf(rz1,wB.z,wB.w))),0.f));
    }

    // ---- dual GEMM: D1 = t@Wp2, D2 = t@Wfuse ----
    float D1[8][4], D2[8][4];
    wgemm2r(At, sW1, sW2, lane, D1, D2);

    // ---- epi1a: gather g = bdst - bsrc + cfuse, edge-major into scr ----
#pragma unroll
    for (int h = 0; h < 2; h++) {
#pragma unroll
      for (int s4 = 0; s4 < 4; s4++) {
        int e = s4*4 + eg;
        int dn = sD[e], sn = sS[e];
        int cg = h*32 + c8*4;
        float4 bd = *(const float4*)(g_bdst + dn*64 + cg);
        float4 bs = *(const float4*)(g_bsrc + sn*64 + cg);
        float4 cf = *(const float4*)(scf + cg);
        *(float4*)(scr + e*72 + cg) = make_float4(
            bd.x - bs.x + cf.x, bd.y - bs.y + cf.y,
            bd.z - bs.z + cf.z, bd.w - bs.w + cf.w);
      }
    }
    __syncwarp();

    // ---- epi1b: u = relu(D2 + g) in D-layout, shfl-transpose to A-layout ----
    uint32_t Au[8][4];
#pragma unroll
    for (int n8 = 0; n8 < 8; n8++) {
      float2 g0 = *(const float2*)(scr + r*72 + n8*8 + 2*q);
      float2 g1 = *(const float2*)(scr + (r+8)*72 + n8*8 + 2*q);
      uint32_t u0 = f2tf(fmaxf(D2[n8][0] + g0.x, 0.f));
      uint32_t u1 = f2tf(fmaxf(D2[n8][1] + g0.y, 0.f));
      uint32_t u2 = f2tf(fmaxf(D2[n8][2] + g1.x, 0.f));
      uint32_t u3 = f2tf(fmaxf(D2[n8][3] + g1.y, 0.f));
      uint32_t v0 = __shfl_sync(0xFFFFFFFFu, u0, Slo);
      uint32_t v1 = __shfl_sync(0xFFFFFFFFu, u1, Slo);
      Au[n8][0] = odd ? v1 : v0;
      uint32_t v2 = __shfl_sync(0xFFFFFFFFu, u2, Slo);
      uint32_t v3 = __shfl_sync(0xFFFFFFFFu, u3, Slo);
      Au[n8][1] = odd ? v3 : v2;
      uint32_t w0 = __shfl_sync(0xFFFFFFFFu, u0, Shi);
      uint32_t w1 = __shfl_sync(0xFFFFFFFFu, u1, Shi);
      Au[n8][2] = odd ? w1 : w0;
      uint32_t w2 = __shfl_sync(0xFFFFFFFFu, u2, Shi);
      uint32_t w3 = __shfl_sync(0xFFFFFFFFu, u3, Shi);
      Au[n8][3] = odd ? w3 : w2;
    }
    __syncwarp();

    // ---- D3 = u@Wa2 ----
    float D3[8][4];
    wgemmr(Au, sW3, lane, D3);

    // ---- epi2: e = exp(D3+ba2); red g_sum += e; g_num += e*(v+D1+bp2) ----
    float* sH1 = scr;          // D1 half 16x40
    float* sH3 = scr + 640;    // D3 half 16x40
#pragma unroll
    for (int h = 0; h < 2; h++) {
#pragma unroll
      for (int n8l = 0; n8l < 4; n8l++) {
        int n8 = h*4 + n8l;
        *(float2*)(sH1 + r*40 + n8l*8 + 2*q)     = make_float2(D1[n8][0], D1[n8][1]);
        *(float2*)(sH1 + (r+8)*40 + n8l*8 + 2*q) = make_float2(D1[n8][2], D1[n8][3]);
        *(float2*)(sH3 + r*40 + n8l*8 + 2*q)     = make_float2(D3[n8][0], D3[n8][1]);
        *(float2*)(sH3 + (r+8)*40 + n8l*8 + 2*q) = make_float2(D3[n8][2], D3[n8][3]);
      }
      __syncwarp();
#pragma unroll
      for (int s4 = 0; s4 < 4; s4++) {
        int e = s4*4 + eg;
        int dn = sD[e], sn = sS[e];
        int cg = h*32 + c8*4;
        float4 lg = *(const float4*)(sH3 + e*40 + c8*4);
        float4 d1 = *(const float4*)(sH1 + e*40 + c8*4);
        float4 vv = *(const float4*)(g_v + sn*64 + cg);
        float4 ba = *(const float4*)(sba2 + cg);
        float4 bp = *(const float4*)(sbp2 + cg);
        float e0 = __expf(lg.x + ba.x);
        float e1 = __expf(lg.y + ba.y);
        float e2 = __expf(lg.z + ba.z);
        float e3 = __expf(lg.w + ba.w);
        redv4(g_sum + dn*64 + cg, e0, e1, e2, e3);
        redv4(g_num + dn*64 + cg,
              e0 * (vv.x + d1.x + bp.x), e1 * (vv.y + d1.y + bp.y),
              e2 * (vv.z + d1.z + bp.z), e3 * (vv.w + d1.w + bp.w));
      }
      __syncwarp();
    }
  }
}

// ---------------- K3: out = relu((num/(sum+eps))@W_out + b_out) -------------
__global__ __launch_bounds__(256) void k_final(const float* __restrict__ Wout,
                                               const float* __restrict__ bout,
                                               float* __restrict__ out) {
  __shared__ float sW[4096];
  __shared__ float sB[64];
  __shared__ float sAT[64*LDA];
  int tid = threadIdx.x;
  int tx = tid & 15, ty = tid >> 4;
  int nbase = blockIdx.x * 64;
#pragma unroll
  for (int t = 0; t < 4; t++) {
    int lin = t*256 + tid;
    int n  = lin >> 4;
    int kk = (lin & 15) << 2;
    float4 v = make_float4(0.f,0.f,0.f,0.f);
    if (nbase + n < NN) {
      float4 num = *(const float4*)(g_num + (nbase+n)*64 + kk);
      float4 s   = *(const float4*)(g_sum + (nbase+n)*64 + kk);
      v.x = num.x / (s.x + 1e-16f);
      v.y = num.y / (s.y + 1e-16f);
      v.z = num.z / (s.z + 1e-16f);
      v.w = num.w / (s.w + 1e-16f);
    }
    sAT[(kk+0)*LDA + n] = v.x;
    sAT[(kk+1)*LDA + n] = v.y;
    sAT[(kk+2)*LDA + n] = v.z;
    sAT[(kk+3)*LDA + n] = v.w;
  }
#pragma unroll
  for (int t = 0; t < 16; t++) sW[t*256 + tid] = Wout[t*256 + tid];
  if (tid < 64) sB[tid] = bout[tid];
  __syncthreads();
  float acc[4][4];
  gemm64(sAT, sW, tx, ty, acc);
#pragma unroll
  for (int i = 0; i < 4; i++) {
    int n = nbase + tx*4 + i;
    if (n < NN) {
      float4 o;
      o.x = fmaxf(acc[i][0] + sB[ty*4+0], 0.f);
      o.y = fmaxf(acc[i][1] + sB[ty*4+1], 0.f);
      o.z = fmaxf(acc[i][2] + sB[ty*4+2], 0.f);
      o.w = fmaxf(acc[i][3] + sB[ty*4+3], 0.f);
      *(float4*)(out + n*64 + ty*4) = o;
    }
  }
}

// ---------------- launch ----------------
extern "C" void kernel_launch(void* const* d_in, const int* in_sizes, int n_in,
                              void* d_out, int out_size) {
  const float* x    = (const float*)d_in[0];
  const float* pos  = (const float*)d_in[1];
  const int*   eidx = (const int*)  d_in[2];
  const float* W_in = (const float*)d_in[3];
  const float* b_in = (const float*)d_in[4];
  const float* W_lin= (const float*)d_in[5];
  const float* W_src= (const float*)d_in[6];
  const float* W_dst= (const float*)d_in[7];
  const float* Wp1  = (const float*)d_in[8];
  const float* bp1  = (const float*)d_in[9];
  const float* Wp2  = (const float*)d_in[10];
  const float* bp2  = (const float*)d_in[11];
  const float* Wa1  = (const float*)d_in[12];
  const float* ba1  = (const float*)d_in[13];
  const float* Wa2  = (const float*)d_in[14];
  const float* ba2  = (const float*)d_in[15];
  const float* W_out= (const float*)d_in[16];
  const float* b_out= (const float*)d_in[17];
  float* out = (float*)d_out;

  const int EDGE_SMEM = SM_WORDS * 4;   // 102656 B
  cudaFuncSetAttribute(k_edge, cudaFuncAttributeMaxDynamicSharedMemorySize,
                       EDGE_SMEM);

  kw<<<3, 256>>>(W_src, W_dst, Wp2, Wa1, bp2, ba1);
  k_node<<<(NN + 63) / 64, 256>>>(x, W_in, b_in, W_lin);
  k_edge<<<296, 256, EDGE_SMEM>>>(pos, eidx, Wp1, bp1, bp2, Wp2, Wa2, ba2);
  k_final<<<(NN + 63) / 64, 256>>>(W_out, b_out, out);
}

// round 9
// speedup vs baseline: 3.8398x; 1.1570x over previous
#include <cuda_runtime.h>
#include <math.h>
#include <stdint.h>

#define NN 50000
#define EE 800000
#define CC 64
#define LDA 68
#define NT16 50000          // EE/16 warp tiles

// -------- device scratch --------
__device__ float g_v[NN*CC];
__device__ float g_bsrc[NN*CC];    // h@(W_src@Wa1)
__device__ float g_bdst[NN*CC];    // h@(W_dst@Wa1)
__device__ float g_sum[NN*CC];     // softmax denominator
__device__ float g_num[NN*CC];     // unnormalized numerator
__device__ float g_Wsa[CC*CC];     // W_src@Wa1
__device__ float g_Wda[CC*CC];     // W_dst@Wa1
__device__ float g_Wfuse[CC*CC];   // Wp2@Wa1
__device__ float g_cfuse[CC];      // bp2@Wa1 + ba1

// ================= mma.sync bf16 helpers =================
__device__ __forceinline__ uint32_t packbf(float lo, float hi) {
  uint32_t o;
  asm("cvt.rn.bf16x2.f32 %0, %1, %2;" : "=r"(o) : "f"(hi), "f"(lo));
  return o;
}
__device__ __forceinline__ void mma16(float c[4], uint32_t a0, uint32_t a1,
                                      uint32_t a2, uint32_t a3,
                                      uint32_t b0, uint32_t b1) {
  asm volatile(
      "mma.sync.aligned.m16n8k16.row.col.f32.bf16.bf16.f32 "
      "{%0,%1,%2,%3}, {%4,%5,%6,%7}, {%8,%9}, {%0,%1,%2,%3};"
      : "+f"(c[0]), "+f"(c[1]), "+f"(c[2]), "+f"(c[3])
      : "r"(a0), "r"(a1), "r"(a2), "r"(a3), "r"(b0), "r"(b1));
}
__device__ __forceinline__ void redv4(float* p, float a, float b, float c, float d) {
  asm volatile("red.global.add.v4.f32 [%0], {%1,%2,%3,%4};"
               :: "l"(p), "f"(a), "f"(b), "f"(c), "f"(d) : "memory");
}

// Dual warp GEMM, A in registers, B1|B2 interleaved uint4 per fragment pair:
// word layout: [(ks*8+n8)*128 + lane*4 + {B1.b0, B1.b1, B2.b0, B2.b1}]
__device__ __forceinline__ void wgemm2rb(const uint32_t A[4][4],
                                         const uint32_t* __restrict__ sW12,
                                         int lane, float D1[8][4], float D2[8][4]) {
#pragma unroll
  for (int n8 = 0; n8 < 8; n8++)
#pragma unroll
    for (int j = 0; j < 4; j++) { D1[n8][j] = 0.f; D2[n8][j] = 0.f; }
#pragma unroll
  for (int ks = 0; ks < 4; ks++) {
    const uint32_t* b = sW12 + (ks<<10) + (lane<<2);
#pragma unroll
    for (int n8 = 0; n8 < 8; n8++) {
      uint4 w = *(const uint4*)(b + (n8<<7));
      mma16(D1[n8], A[ks][0], A[ks][1], A[ks][2], A[ks][3], w.x, w.y);
      mma16(D2[n8], A[ks][0], A[ks][1], A[ks][2], A[ks][3], w.z, w.w);
    }
  }
}
// Single warp GEMM: frag(ks,n8) at (ks*8+n8)*64 + lane*2 (uint2)
__device__ __forceinline__ void wgemmrb(const uint32_t A[4][4],
                                        const uint32_t* __restrict__ sB,
                                        int lane, float D[8][4]) {
#pragma unroll
  for (int n8 = 0; n8 < 8; n8++)
#pragma unroll
    for (int j = 0; j < 4; j++) D[n8][j] = 0.f;
#pragma unroll
  for (int ks = 0; ks < 4; ks++) {
    const uint32_t* bb = sB + (ks<<9) + (lane<<1);
#pragma unroll
    for (int n8 = 0; n8 < 8; n8++) {
      uint2 w = *(const uint2*)(bb + (n8<<6));
      mma16(D[n8], A[ks][0], A[ks][1], A[ks][2], A[ks][3], w.x, w.y);
    }
  }
}

// ================= fp32 64x64x64 register-tiled GEMM core =================
__device__ __forceinline__ void gemm64(const float* __restrict__ sAT,
                                       const float* __restrict__ sW,
                                       int tx, int ty, float acc[4][4]) {
#pragma unroll
  for (int i = 0; i < 4; i++)
#pragma unroll
    for (int j = 0; j < 4; j++) acc[i][j] = 0.f;
#pragma unroll 8
  for (int k = 0; k < 64; k++) {
    float4 a = *(const float4*)(sAT + k*LDA + tx*4);
    float4 b = *(const float4*)(sW  + k*64  + ty*4);
    acc[0][0] = fmaf(a.x, b.x, acc[0][0]);
    acc[0][1] = fmaf(a.x, b.y, acc[0][1]);
    acc[0][2] = fmaf(a.x, b.z, acc[0][2]);
    acc[0][3] = fmaf(a.x, b.w, acc[0][3]);
    acc[1][0] = fmaf(a.y, b.x, acc[1][0]);
    acc[1][1] = fmaf(a.y, b.y, acc[1][1]);
    acc[1][2] = fmaf(a.y, b.z, acc[1][2]);
    acc[1][3] = fmaf(a.y, b.w, acc[1][3]);
    acc[2][0] = fmaf(a.z, b.x, acc[2][0]);
    acc[2][1] = fmaf(a.z, b.y, acc[2][1]);
    acc[2][2] = fmaf(a.z, b.z, acc[2][2]);
    acc[2][3] = fmaf(a.z, b.w, acc[2][3]);
    acc[3][0] = fmaf(a.w, b.x, acc[3][0]);
    acc[3][1] = fmaf(a.w, b.y, acc[3][1]);
    acc[3][2] = fmaf(a.w, b.z, acc[3][2]);
    acc[3][3] = fmaf(a.w, b.w, acc[3][3]);
  }
}

// ---------------- KW: weight precompute ----------------
__global__ __launch_bounds__(256) void kw(const float* __restrict__ Wsrc,
    const float* __restrict__ Wdst, const float* __restrict__ Wp2,
    const float* __restrict__ Wa1, const float* __restrict__ bp2,
    const float* __restrict__ ba1) {
  __shared__ float sWa1[4096];
  int tid = threadIdx.x;
#pragma unroll
  for (int t = 0; t < 16; t++) sWa1[t*256 + tid] = Wa1[t*256 + tid];
  __syncthreads();
  const float* A = (blockIdx.x == 0) ? Wsrc : (blockIdx.x == 1) ? Wdst : Wp2;
  float* O = (blockIdx.x == 0) ? g_Wsa : (blockIdx.x == 1) ? g_Wda : g_Wfuse;
  for (int idx = tid; idx < 4096; idx += 256) {
    int k = idx >> 6, n = idx & 63;
    float s = 0.f;
#pragma unroll 16
    for (int m = 0; m < 64; m++) s = fmaf(A[k*64 + m], sWa1[m*64 + n], s);
    O[idx] = s;
  }
  if (blockIdx.x == 2 && tid < 64) {
    float s = ba1[tid];
#pragma unroll 16
    for (int m = 0; m < 64; m++) s = fmaf(bp2[m], sWa1[m*64 + tid], s);
    g_cfuse[tid] = s;
  }
}

// ---------------- K1: node projections + accumulator zeroing ----------------
__global__ __launch_bounds__(256) void k_node(const float* __restrict__ x,
    const float* __restrict__ Win, const float* __restrict__ bin,
    const float* __restrict__ Wlin) {
  __shared__ float sW[4096];
  __shared__ float sB[64];
  __shared__ float sAT[64*LDA];
  int tid = threadIdx.x;
  int tx = tid & 15, ty = tid >> 4;
  int nbase = blockIdx.x * 64;

  // zero g_sum/g_num for this node tile
  {
    float4 z = make_float4(0.f,0.f,0.f,0.f);
#pragma unroll
    for (int j = 0; j < 4; j++) {
      int off = tid*16 + j*4;
      int n = nbase + (off >> 6);
      if (n < NN) {
        *(float4*)(g_sum + nbase*64 + off) = z;
        *(float4*)(g_num + nbase*64 + off) = z;
      }
    }
  }

#pragma unroll
  for (int t = 0; t < 4; t++) {
    int lin = t*256 + tid;
    int n  = lin >> 4;
    int kk = (lin & 15) << 2;
    float4 v = make_float4(0.f,0.f,0.f,0.f);
    if (nbase + n < NN) v = *(const float4*)(x + (nbase+n)*64 + kk);
    sAT[(kk+0)*LDA + n] = v.x;
    sAT[(kk+1)*LDA + n] = v.y;
    sAT[(kk+2)*LDA + n] = v.z;
    sAT[(kk+3)*LDA + n] = v.w;
  }
#pragma unroll
  for (int t = 0; t < 16; t++) sW[t*256 + tid] = Win[t*256 + tid];
  if (tid < 64) sB[tid] = bin[tid];
  __syncthreads();

  float acc[4][4];
  gemm64(sAT, sW, tx, ty, acc);
  __syncthreads();

#pragma unroll
  for (int j = 0; j < 4; j++)
#pragma unroll
    for (int i = 0; i < 4; i++)
      sAT[(ty*4+j)*LDA + tx*4+i] = fmaxf(acc[i][j] + sB[ty*4+j], 0.f);
  __syncthreads();

#pragma unroll
  for (int m = 0; m < 3; m++) {
    const float* Wm = (m==0) ? Wlin : (m==1) ? g_Wsa : g_Wda;
    float*       Om = (m==0) ? g_v  : (m==1) ? g_bsrc : g_bdst;
#pragma unroll
    for (int t = 0; t < 16; t++) sW[t*256 + tid] = Wm[t*256 + tid];
    __syncthreads();
    gemm64(sAT, sW, tx, ty, acc);
#pragma unroll
    for (int i = 0; i < 4; i++) {
      int n = nbase + tx*4 + i;
      if (n < NN)
        *(float4*)(Om + n*64 + ty*4) =
            make_float4(acc[i][0], acc[i][1], acc[i][2], acc[i][3]);
    }
    __syncthreads();
  }
}

// ---------------- K2: fused edge kernel (bf16 m16n8k16) ----------------
// smem words:
//  [0,4096)        Wp2|Wfuse interleaved bf16 frag pairs (uint4/lane)
//  [4096,6144)     Wa2 bf16 frag-linear (uint2/lane)
//  [6144,18432)    8 per-warp scratch (1536 each): g[16x76] / epi2 2x[16x40]
//  [18432,18688)   Wp1 packed float4 per col: {w0,w1,w2,bp1}
//  [18688,18752)   bp2
//  [18752,18816)   ba2
//  [18816,18880)   cfuse
//  [18880,19264)   8 per-warp rel (48 each)
//  [19264,19520)   8 per-warp src/dst (32 each)
#define SM_WORDS 19520
__global__ void __launch_bounds__(256, 2) k_edge(
    const float* __restrict__ pos, const int* __restrict__ eidx,
    const float* __restrict__ Wp1, const float* __restrict__ bp1,
    const float* __restrict__ bp2, const float* __restrict__ Wp2,
    const float* __restrict__ Wa2, const float* __restrict__ ba2) {
  extern __shared__ uint32_t smu[];
  uint32_t* sW12  = smu;                    // 4096
  uint32_t* sW3   = smu + 4096;             // 2048
  float*    sScr  = (float*)(smu + 6144);   // 12288
  float4*   sWp1p = (float4*)(smu + 18432); // 64 float4
  float* sbp2 = (float*)(smu + 18688);
  float* sba2 = (float*)(smu + 18752);
  float* scf  = (float*)(smu + 18816);
  float* sRelAll = (float*)(smu + 18880);
  int*   sIdxAll = (int*)(smu + 19264);

  int tid = threadIdx.x;
  int wid = tid >> 5, lane = tid & 31;

  // stage bf16 B fragments.
  // frag(ks,n8), lane ln=(rr<<2)|qq, reg t: {W[16ks+2qq+8t][8n8+rr], W[..+1][..]}
  for (int idx = tid; idx < 2048; idx += 256) {
    int t  = idx & 1;
    int ln = (idx >> 1) & 31;
    int fr = idx >> 6;
    int ks = fr >> 3, n8 = fr & 7;
    int rr = ln >> 2, qq = ln & 3;
    int klo = 16*ks + 2*qq + t*8;
    int col = 8*n8 + rr;
    uint32_t w1 = packbf(Wp2[klo*64 + col],     Wp2[(klo+1)*64 + col]);
    uint32_t w2 = packbf(g_Wfuse[klo*64 + col], g_Wfuse[(klo+1)*64 + col]);
    uint32_t w3 = packbf(Wa2[klo*64 + col],     Wa2[(klo+1)*64 + col]);
    int base12 = (fr << 7) + (ln << 2);
    sW12[base12 + t]     = w1;
    sW12[base12 + 2 + t] = w2;
    sW3[(fr << 6) + (ln << 1) + t] = w3;
  }
  if (tid < 64) {
    sWp1p[tid] = make_float4(Wp1[tid], Wp1[64+tid], Wp1[128+tid], bp1[tid]);
    sbp2[tid] = bp2[tid]; sba2[tid] = ba2[tid]; scf[tid] = g_cfuse[tid];
  }
  __syncthreads();

  float* scr = sScr + wid*1536;       // g: 16x76; epi2: [0,640) D1h, [640,1280) D3h
  float* sRel = sRelAll + wid*48;
  int* sS = sIdxAll + wid*32;
  int* sD = sS + 16;

  int r = lane >> 2, q = lane & 3;
  int eg = lane >> 3, c8 = lane & 7;    // edge-major epilogue mapping

  int gw = blockIdx.x * 8 + wid;
  int nwarp = gridDim.x * 8;
  for (int t = gw; t < NT16; t += nwarp) {
    int eb = t * 16;
    if (lane < 16) sS[lane] = eidx[eb + lane];
    else           sD[lane - 16] = eidx[EE + eb + (lane - 16)];
    __syncwarp();
    if (lane < 16) {
      int s = sS[lane], d = sD[lane];
      sRel[lane]      = pos[d*3+0] - pos[s*3+0];
      sRel[16 + lane] = pos[d*3+1] - pos[s*3+1];
      sRel[32 + lane] = pos[d*3+2] - pos[s*3+2];
    }
    __syncwarp();

    // ---- t-fragments (bf16) directly in registers ----
    float rx0 = sRel[r],     ry0 = sRel[16+r],   rz0 = sRel[32+r];
    float rx1 = sRel[r+8],   ry1 = sRel[16+r+8], rz1 = sRel[32+r+8];
    uint32_t At[4][4];
#pragma unroll
    for (int ks = 0; ks < 4; ks++) {
      float4 wA = sWp1p[16*ks + 2*q];
      float4 wB = sWp1p[16*ks + 2*q + 1];
      float4 wC = sWp1p[16*ks + 2*q + 8];
      float4 wD = sWp1p[16*ks + 2*q + 9];
      float tA0 = fmaxf(fmaf(rx0,wA.x,fmaf(ry0,wA.y,fmaf(rz0,wA.z,wA.w))),0.f);
      float tB0 = fmaxf(fmaf(rx0,wB.x,fmaf(ry0,wB.y,fmaf(rz0,wB.z,wB.w))),0.f);
      float tA1 = fmaxf(fmaf(rx1,wA.x,fmaf(ry1,wA.y,fmaf(rz1,wA.z,wA.w))),0.f);
      float tB1 = fmaxf(fmaf(rx1,wB.x,fmaf(ry1,wB.y,fmaf(rz1,wB.z,wB.w))),0.f);
      float tC0 = fmaxf(fmaf(rx0,wC.x,fmaf(ry0,wC.y,fmaf(rz0,wC.z,wC.w))),0.f);
      float tD0 = fmaxf(fmaf(rx0,wD.x,fmaf(ry0,wD.y,fmaf(rz0,wD.z,wD.w))),0.f);
      float tC1 = fmaxf(fmaf(rx1,wC.x,fmaf(ry1,wC.y,fmaf(rz1,wC.z,wC.w))),0.f);
      float tD1 = fmaxf(fmaf(rx1,wD.x,fmaf(ry1,wD.y,fmaf(rz1,wD.z,wD.w))),0.f);
      At[ks][0] = packbf(tA0, tB0);
      At[ks][1] = packbf(tA1, tB1);
      At[ks][2] = packbf(tC0, tD0);
      At[ks][3] = packbf(tC1, tD1);
    }

    // ---- dual GEMM: D1 = t@Wp2, D2 = t@Wfuse ----
    float D1[8][4], D2[8][4];
    wgemm2rb(At, sW12, lane, D1, D2);

    // ---- epi1a: gather g = bdst - bsrc + cfuse, edge-major into scr ----
#pragma unroll
    for (int h = 0; h < 2; h++) {
#pragma unroll
      for (int s4 = 0; s4 < 4; s4++) {
        int e = s4*4 + eg;
        int dn = sD[e], sn = sS[e];
        int cg = h*32 + c8*4;
        float4 bd = *(const float4*)(g_bdst + dn*64 + cg);
        float4 bs = *(const float4*)(g_bsrc + sn*64 + cg);
        float4 cf = *(const float4*)(scf + cg);
        *(float4*)(scr + e*76 + cg) = make_float4(
            bd.x - bs.x + cf.x, bd.y - bs.y + cf.y,
            bd.z - bs.z + cf.z, bd.w - bs.w + cf.w);
      }
    }
    __syncwarp();

    // ---- epi1b: u = relu(D2 + g); D-layout packs straight into A-frags ----
    uint32_t Au[4][4];
#pragma unroll
    for (int ks = 0; ks < 4; ks++) {
      int na = 2*ks, nb = 2*ks + 1;
      float2 g0a = *(const float2*)(scr + r*76 + na*8 + 2*q);
      float2 g1a = *(const float2*)(scr + (r+8)*76 + na*8 + 2*q);
      float2 g0b = *(const float2*)(scr + r*76 + nb*8 + 2*q);
      float2 g1b = *(const float2*)(scr + (r+8)*76 + nb*8 + 2*q);
      Au[ks][0] = packbf(fmaxf(D2[na][0] + g0a.x, 0.f),
                         fmaxf(D2[na][1] + g0a.y, 0.f));
      Au[ks][1] = packbf(fmaxf(D2[na][2] + g1a.x, 0.f),
                         fmaxf(D2[na][3] + g1a.y, 0.f));
      Au[ks][2] = packbf(fmaxf(D2[nb][0] + g0b.x, 0.f),
                         fmaxf(D2[nb][1] + g0b.y, 0.f));
      Au[ks][3] = packbf(fmaxf(D2[nb][2] + g1b.x, 0.f),
                         fmaxf(D2[nb][3] + g1b.y, 0.f));
    }
    __syncwarp();

    // ---- D3 = u@Wa2 ----
    float D3[8][4];
    wgemmrb(Au, sW3, lane, D3);

    // ---- epi2: e = exp(D3+ba2); red g_sum += e; g_num += e*(v+D1+bp2) ----
    float* sH1 = scr;          // D1 half 16x40
    float* sH3 = scr + 640;    // D3 half 16x40
#pragma unroll
    for (int h = 0; h < 2; h++) {
#pragma unroll
      for (int n8l = 0; n8l < 4; n8l++) {
        int n8 = h*4 + n8l;
        *(float2*)(sH1 + r*40 + n8l*8 + 2*q)     = make_float2(D1[n8][0], D1[n8][1]);
        *(float2*)(sH1 + (r+8)*40 + n8l*8 + 2*q) = make_float2(D1[n8][2], D1[n8][3]);
        *(float2*)(sH3 + r*40 + n8l*8 + 2*q)     = make_float2(D3[n8][0], D3[n8][1]);
        *(float2*)(sH3 + (r+8)*40 + n8l*8 + 2*q) = make_float2(D3[n8][2], D3[n8][3]);
      }
      __syncwarp();
#pragma unroll
      for (int s4 = 0; s4 < 4; s4++) {
        int e = s4*4 + eg;
        int dn = sD[e], sn = sS[e];
        int cg = h*32 + c8*4;
        float4 lg = *(const float4*)(sH3 + e*40 + c8*4);
        float4 d1 = *(const float4*)(sH1 + e*40 + c8*4);
        float4 vv = *(const float4*)(g_v + sn*64 + cg);
        float4 ba = *(const float4*)(sba2 + cg);
        float4 bp = *(const float4*)(sbp2 + cg);
        float e0 = __expf(lg.x + ba.x);
        float e1 = __expf(lg.y + ba.y);
        float e2 = __expf(lg.z + ba.z);
        float e3 = __expf(lg.w + ba.w);
        redv4(g_sum + dn*64 + cg, e0, e1, e2, e3);
        redv4(g_num + dn*64 + cg,
              e0 * (vv.x + d1.x + bp.x), e1 * (vv.y + d1.y + bp.y),
              e2 * (vv.z + d1.z + bp.z), e3 * (vv.w + d1.w + bp.w));
      }
      __syncwarp();
    }
  }
}

// ---------------- K3: out = relu((num/(sum+eps))@W_out + b_out) -------------
__global__ __launch_bounds__(256) void k_final(const float* __restrict__ Wout,
                                               const float* __restrict__ bout,
                                               float* __restrict__ out) {
  __shared__ float sW[4096];
  __shared__ float sB[64];
  __shared__ float sAT[64*LDA];
  int tid = threadIdx.x;
  int tx = tid & 15, ty = tid >> 4;
  int nbase = blockIdx.x * 64;
#pragma unroll
  for (int t = 0; t < 4; t++) {
    int lin = t*256 + tid;
    int n  = lin >> 4;
    int kk = (lin & 15) << 2;
    float4 v = make_float4(0.f,0.f,0.f,0.f);
    if (nbase + n < NN) {
      float4 num = *(const float4*)(g_num + (nbase+n)*64 + kk);
      float4 s   = *(const float4*)(g_sum + (nbase+n)*64 + kk);
      v.x = num.x / (s.x + 1e-16f);
      v.y = num.y / (s.y + 1e-16f);
      v.z = num.z / (s.z + 1e-16f);
      v.w = num.w / (s.w + 1e-16f);
    }
    sAT[(kk+0)*LDA + n] = v.x;
    sAT[(kk+1)*LDA + n] = v.y;
    sAT[(kk+2)*LDA + n] = v.z;
    sAT[(kk+3)*LDA + n] = v.w;
  }
#pragma unroll
  for (int t = 0; t < 16; t++) sW[t*256 + tid] = Wout[t*256 + tid];
  if (tid < 64) sB[tid] = bout[tid];
  __syncthreads();
  float acc[4][4];
  gemm64(sAT, sW, tx, ty, acc);
#pragma unroll
  for (int i = 0; i < 4; i++) {
    int n = nbase + tx*4 + i;
    if (n < NN) {
      float4 o;
      o.x = fmaxf(acc[i][0] + sB[ty*4+0], 0.f);
      o.y = fmaxf(acc[i][1] + sB[ty*4+1], 0.f);
      o.z = fmaxf(acc[i][2] + sB[ty*4+2], 0.f);
      o.w = fmaxf(acc[i][3] + sB[ty*4+3], 0.f);
      *(float4*)(out + n*64 + ty*4) = o;
    }
  }
}

// ---------------- launch ----------------
extern "C" void kernel_launch(void* const* d_in, const int* in_sizes, int n_in,
                              void* d_out, int out_size) {
  const float* x    = (const float*)d_in[0];
  const float* pos  = (const float*)d_in[1];
  const int*   eidx = (const int*)  d_in[2];
  const float* W_in = (const float*)d_in[3];
  const float* b_in = (const float*)d_in[4];
  const float* W_lin= (const float*)d_in[5];
  const float* W_src= (const float*)d_in[6];
  const float* W_dst= (const float*)d_in[7];
  const float* Wp1  = (const float*)d_in[8];
  const float* bp1  = (const float*)d_in[9];
  const float* Wp2  = (const float*)d_in[10];
  const float* bp2  = (const float*)d_in[11];
  const float* Wa1  = (const float*)d_in[12];
  const float* ba1  = (const float*)d_in[13];
  const float* Wa2  = (const float*)d_in[14];
  const float* ba2  = (const float*)d_in[15];
  const float* W_out= (const float*)d_in[16];
  const float* b_out= (const float*)d_in[17];
  float* out = (float*)d_out;

  const int EDGE_SMEM = SM_WORDS * 4;   // 78080 B
  cudaFuncSetAttribute(k_edge, cudaFuncAttributeMaxDynamicSharedMemorySize,
                       EDGE_SMEM);

  kw<<<3, 256>>>(W_src, W_dst, Wp2, Wa1, bp2, ba1);
  k_node<<<(NN + 63) / 64, 256>>>(x, W_in, b_in, W_lin);
  k_edge<<<296, 256, EDGE_SMEM>>>(pos, eidx, Wp1, bp1, bp2, Wp2, Wa2, ba2);
  k_final<<<(NN + 63) / 64, 256>>>(W_out, b_out, out);
}

// round 10
// speedup vs baseline: 3.8684x; 1.0074x over previous
#include <cuda_runtime.h>
#include <math.h>
#include <stdint.h>

#define NN 50000
#define EE 800000
#define CC 64
#define NT16 50000          // EE/16 warp tiles

// -------- device scratch --------
__device__ float g_v[NN*CC];
__device__ float g_bsrc[NN*CC];    // h@(W_src@Wa1)
__device__ float g_bdst[NN*CC];    // h@(W_dst@Wa1)
__device__ float g_sum[NN*CC];     // softmax denominator
__device__ float g_num[NN*CC];     // unnormalized numerator
__device__ float g_Wsa[CC*CC];     // W_src@Wa1
__device__ float g_Wda[CC*CC];     // W_dst@Wa1
__device__ float g_Wfuse[CC*CC];   // Wp2@Wa1
__device__ float g_cfuse[CC];      // bp2@Wa1 + ba1

// ================= mma.sync helpers =================
__device__ __forceinline__ uint32_t f2tf(float f) {
  uint32_t o;
  asm("cvt.rna.tf32.f32 %0, %1;" : "=r"(o) : "f"(f));
  return o;
}
__device__ __forceinline__ uint32_t packbf(float lo, float hi) {
  uint32_t o;
  asm("cvt.rn.bf16x2.f32 %0, %1, %2;" : "=r"(o) : "f"(hi), "f"(lo));
  return o;
}
__device__ __forceinline__ void mma8(float c[4], uint32_t a0, uint32_t a1,
                                     uint32_t a2, uint32_t a3,
                                     uint32_t b0, uint32_t b1) {
  asm volatile(
      "mma.sync.aligned.m16n8k8.row.col.f32.tf32.tf32.f32 "
      "{%0,%1,%2,%3}, {%4,%5,%6,%7}, {%8,%9}, {%0,%1,%2,%3};"
      : "+f"(c[0]), "+f"(c[1]), "+f"(c[2]), "+f"(c[3])
      : "r"(a0), "r"(a1), "r"(a2), "r"(a3), "r"(b0), "r"(b1));
}
__device__ __forceinline__ void mma16(float c[4], uint32_t a0, uint32_t a1,
                                      uint32_t a2, uint32_t a3,
                                      uint32_t b0, uint32_t b1) {
  asm volatile(
      "mma.sync.aligned.m16n8k16.row.col.f32.bf16.bf16.f32 "
      "{%0,%1,%2,%3}, {%4,%5,%6,%7}, {%8,%9}, {%0,%1,%2,%3};"
      : "+f"(c[0]), "+f"(c[1]), "+f"(c[2]), "+f"(c[3])
      : "r"(a0), "r"(a1), "r"(a2), "r"(a3), "r"(b0), "r"(b1));
}
__device__ __forceinline__ void redv4(float* p, float a, float b, float c, float d) {
  asm volatile("red.global.add.v4.f32 [%0], {%1,%2,%3,%4};"
               :: "l"(p), "f"(a), "f"(b), "f"(c), "f"(d) : "memory");
}

// ---- tf32 warp GEMM, A in regs, B frag-linear: frag(k8,n8) @ (k8*8+n8)*64 + lane*2
__device__ __forceinline__ void wgemmr_tf(const uint32_t A[8][4],
                                          const uint32_t* __restrict__ sB,
                                          int lane, float D[8][4]) {
#pragma unroll
  for (int n8 = 0; n8 < 8; n8++)
#pragma unroll
    for (int j = 0; j < 4; j++) D[n8][j] = 0.f;
#pragma unroll
  for (int k8 = 0; k8 < 8; k8++) {
    const uint32_t* bb = sB + (k8<<9) + (lane<<1);
#pragma unroll
    for (int n8 = 0; n8 < 8; n8++) {
      uint2 w = *(const uint2*)(bb + (n8<<6));
      mma8(D[n8], A[k8][0], A[k8][1], A[k8][2], A[k8][3], w.x, w.y);
    }
  }
}

// ---- bf16 dual warp GEMM (B1|B2 interleaved uint4) and single GEMM ----
__device__ __forceinline__ void wgemm2rb(const uint32_t A[4][4],
                                         const uint32_t* __restrict__ sW12,
                                         int lane, float D1[8][4], float D2[8][4]) {
#pragma unroll
  for (int n8 = 0; n8 < 8; n8++)
#pragma unroll
    for (int j = 0; j < 4; j++) { D1[n8][j] = 0.f; D2[n8][j] = 0.f; }
#pragma unroll
  for (int ks = 0; ks < 4; ks++) {
    const uint32_t* b = sW12 + (ks<<10) + (lane<<2);
#pragma unroll
    for (int n8 = 0; n8 < 8; n8++) {
      uint4 w = *(const uint4*)(b + (n8<<7));
      mma16(D1[n8], A[ks][0], A[ks][1], A[ks][2], A[ks][3], w.x, w.y);
      mma16(D2[n8], A[ks][0], A[ks][1], A[ks][2], A[ks][3], w.z, w.w);
    }
  }
}
__device__ __forceinline__ void wgemmrb(const uint32_t A[4][4],
                                        const uint32_t* __restrict__ sB,
                                        int lane, float D[8][4]) {
#pragma unroll
  for (int n8 = 0; n8 < 8; n8++)
#pragma unroll
    for (int j = 0; j < 4; j++) D[n8][j] = 0.f;
#pragma unroll
  for (int ks = 0; ks < 4; ks++) {
    const uint32_t* bb = sB + (ks<<9) + (lane<<1);
#pragma unroll
    for (int n8 = 0; n8 < 8; n8++) {
      uint2 w = *(const uint2*)(bb + (n8<<6));
      mma16(D[n8], A[ks][0], A[ks][1], A[ks][2], A[ks][3], w.x, w.y);
    }
  }
}

// stage fp32 weight matrix [64][64] into tf32 frag-linear layout (4096 words)
__device__ __forceinline__ void stage_tf32(const float* __restrict__ W,
                                           uint32_t* __restrict__ dst, int tid) {
  for (int idx = tid; idx < 4096; idx += 256) {
    int tbit = idx & 1;
    int ln   = (idx & 63) >> 1;
    int kn   = idx >> 6;
    int k8 = kn >> 3, n8 = kn & 7;
    int rr = ln >> 2, qq = ln & 3;
    dst[idx] = f2tf(W[(k8*8 + qq + tbit*4)*64 + n8*8 + rr]);
  }
}

// ---------------- KW: weight precompute ----------------
__global__ __launch_bounds__(256) void kw(const float* __restrict__ Wsrc,
    const float* __restrict__ Wdst, const float* __restrict__ Wp2,
    const float* __restrict__ Wa1, const float* __restrict__ bp2,
    const float* __restrict__ ba1) {
  __shared__ float sWa1[4096];
  int tid = threadIdx.x;
#pragma unroll
  for (int t = 0; t < 16; t++) sWa1[t*256 + tid] = Wa1[t*256 + tid];
  __syncthreads();
  const float* A = (blockIdx.x == 0) ? Wsrc : (blockIdx.x == 1) ? Wdst : Wp2;
  float* O = (blockIdx.x == 0) ? g_Wsa : (blockIdx.x == 1) ? g_Wda : g_Wfuse;
  for (int idx = tid; idx < 4096; idx += 256) {
    int k = idx >> 6, n = idx & 63;
    float s = 0.f;
#pragma unroll 16
    for (int m = 0; m < 64; m++) s = fmaf(A[k*64 + m], sWa1[m*64 + n], s);
    O[idx] = s;
  }
  if (blockIdx.x == 2 && tid < 64) {
    float s = ba1[tid];
#pragma unroll 16
    for (int m = 0; m < 64; m++) s = fmaf(bp2[m], sWa1[m*64 + tid], s);
    g_cfuse[tid] = s;
  }
}

// ---------------- K1: node projections (tf32 mma) + accumulator zeroing -----
// 8 warps x 16 nodes per block (128 nodes). smem words:
//  [0,16384)      4 weights frag-linear tf32 (Win|Wlin|Wsa|Wda)
//  [16384,25088)  8 per-warp x stage [16][68]
//  [25088,25152)  b_in
#define NODE_SM 25152
__global__ void __launch_bounds__(256, 1) k_node(const float* __restrict__ x,
    const float* __restrict__ Win, const float* __restrict__ bin,
    const float* __restrict__ Wlin) {
  extern __shared__ uint32_t smn[];
  uint32_t* sWf = smn;
  float* sXall  = (float*)(smn + 16384);
  float* sbin   = (float*)(smn + 25088);

  int tid = threadIdx.x;
  int wid = tid >> 5, lane = tid & 31;
  int nb0 = blockIdx.x * 128;

  // zero g_sum/g_num for this node range
#pragma unroll
  for (int j = 0; j < 8; j++) {
    int idx = j*256 + tid;
    int node = nb0 + (idx >> 4);
    int c4 = (idx & 15) << 2;
    if (node < NN) {
      float4 z = make_float4(0.f,0.f,0.f,0.f);
      *(float4*)(g_sum + node*64 + c4) = z;
      *(float4*)(g_num + node*64 + c4) = z;
    }
  }

  stage_tf32(Win,   sWf,          tid);
  stage_tf32(Wlin,  sWf + 4096,   tid);
  stage_tf32(g_Wsa, sWf + 8192,   tid);
  stage_tf32(g_Wda, sWf + 12288,  tid);
  if (tid < 64) sbin[tid] = bin[tid];
  __syncthreads();

  int nb = nb0 + wid*16;
  if (nb >= NN) return;
  float* sX = sXall + wid*1088;   // 16 x 68

  // stage x rows
  for (int idx = lane; idx < 256; idx += 32) {
    int row = idx >> 4;
    int c4  = (idx & 15) << 2;
    int n = nb + row;
    float4 v = make_float4(0.f,0.f,0.f,0.f);
    if (n < NN) v = *(const float4*)(x + n*64 + c4);
    *(float4*)(sX + row*68 + c4) = v;
  }
  __syncwarp();

  int r = lane >> 2, q = lane & 3;
  int Slo = (lane & ~3) | (q >> 1);
  int Shi = Slo + 2;
  int odd = q & 1;

  // x A-frags
  uint32_t Ax[8][4];
#pragma unroll
  for (int k8 = 0; k8 < 8; k8++) {
    Ax[k8][0] = f2tf(sX[r*68     + k8*8 + q]);
    Ax[k8][1] = f2tf(sX[(r+8)*68 + k8*8 + q]);
    Ax[k8][2] = f2tf(sX[r*68     + k8*8 + q + 4]);
    Ax[k8][3] = f2tf(sX[(r+8)*68 + k8*8 + q + 4]);
  }

  // GEMM1: h = relu(x@Win + bin), then shfl-transpose D->A layout
  float Dh[8][4];
  wgemmr_tf(Ax, sWf, lane, Dh);
  uint32_t Ah[8][4];
#pragma unroll
  for (int n8 = 0; n8 < 8; n8++) {
    int c0 = n8*8 + 2*q, c1 = c0 + 1;
    uint32_t u0 = f2tf(fmaxf(Dh[n8][0] + sbin[c0], 0.f));
    uint32_t u1 = f2tf(fmaxf(Dh[n8][1] + sbin[c1], 0.f));
    uint32_t u2 = f2tf(fmaxf(Dh[n8][2] + sbin[c0], 0.f));
    uint32_t u3 = f2tf(fmaxf(Dh[n8][3] + sbin[c1], 0.f));
    uint32_t v0 = __shfl_sync(0xFFFFFFFFu, u0, Slo);
    uint32_t v1 = __shfl_sync(0xFFFFFFFFu, u1, Slo);
    Ah[n8][0] = odd ? v1 : v0;
    uint32_t v2 = __shfl_sync(0xFFFFFFFFu, u2, Slo);
    uint32_t v3 = __shfl_sync(0xFFFFFFFFu, u3, Slo);
    Ah[n8][1] = odd ? v3 : v2;
    uint32_t w0 = __shfl_sync(0xFFFFFFFFu, u0, Shi);
    uint32_t w1 = __shfl_sync(0xFFFFFFFFu, u1, Shi);
    Ah[n8][2] = odd ? w1 : w0;
    uint32_t w2 = __shfl_sync(0xFFFFFFFFu, u2, Shi);
    uint32_t w3 = __shfl_sync(0xFFFFFFFFu, u3, Shi);
    Ah[n8][3] = odd ? w3 : w2;
  }

  // GEMMs 2-4: v / bsrc / bdst, D-layout float2 stores
  int ok0 = (nb + r < NN), ok1 = (nb + r + 8 < NN);
#pragma unroll
  for (int m = 0; m < 3; m++) {
    float* Om = (m==0) ? g_v : (m==1) ? g_bsrc : g_bdst;
    float D[8][4];
    wgemmr_tf(Ah, sWf + (m+1)*4096, lane, D);
#pragma unroll
    for (int n8 = 0; n8 < 8; n8++) {
      int c0 = n8*8 + 2*q;
      if (ok0) *(float2*)(Om + (nb+r)*64 + c0)   = make_float2(D[n8][0], D[n8][1]);
      if (ok1) *(float2*)(Om + (nb+r+8)*64 + c0) = make_float2(D[n8][2], D[n8][3]);
    }
  }
}

// ---------------- K2: fused edge kernel (bf16 m16n8k16) — unchanged --------
#define SM_WORDS 19520
__global__ void __launch_bounds__(256, 2) k_edge(
    const float* __restrict__ pos, const int* __restrict__ eidx,
    const float* __restrict__ Wp1, const float* __restrict__ bp1,
    const float* __restrict__ bp2, const float* __restrict__ Wp2,
    const float* __restrict__ Wa2, const float* __restrict__ ba2) {
  extern __shared__ uint32_t smu[];
  uint32_t* sW12  = smu;                    // 4096
  uint32_t* sW3   = smu + 4096;             // 2048
  float*    sScr  = (float*)(smu + 6144);   // 12288
  float4*   sWp1p = (float4*)(smu + 18432); // 64 float4
  float* sbp2 = (float*)(smu + 18688);
  float* sba2 = (float*)(smu + 18752);
  float* scf  = (float*)(smu + 18816);
  float* sRelAll = (float*)(smu + 18880);
  int*   sIdxAll = (int*)(smu + 19264);

  int tid = threadIdx.x;
  int wid = tid >> 5, lane = tid & 31;

  for (int idx = tid; idx < 2048; idx += 256) {
    int t  = idx & 1;
    int ln = (idx >> 1) & 31;
    int fr = idx >> 6;
    int ks = fr >> 3, n8 = fr & 7;
    int rr = ln >> 2, qq = ln & 3;
    int klo = 16*ks + 2*qq + t*8;
    int col = 8*n8 + rr;
    uint32_t w1 = packbf(Wp2[klo*64 + col],     Wp2[(klo+1)*64 + col]);
    uint32_t w2 = packbf(g_Wfuse[klo*64 + col], g_Wfuse[(klo+1)*64 + col]);
    uint32_t w3 = packbf(Wa2[klo*64 + col],     Wa2[(klo+1)*64 + col]);
    int base12 = (fr << 7) + (ln << 2);
    sW12[base12 + t]     = w1;
    sW12[base12 + 2 + t] = w2;
    sW3[(fr << 6) + (ln << 1) + t] = w3;
  }
  if (tid < 64) {
    sWp1p[tid] = make_float4(Wp1[tid], Wp1[64+tid], Wp1[128+tid], bp1[tid]);
    sbp2[tid] = bp2[tid]; sba2[tid] = ba2[tid]; scf[tid] = g_cfuse[tid];
  }
  __syncthreads();

  float* scr = sScr + wid*1536;
  float* sRel = sRelAll + wid*48;
  int* sS = sIdxAll + wid*32;
  int* sD = sS + 16;

  int r = lane >> 2, q = lane & 3;
  int eg = lane >> 3, c8 = lane & 7;

  int gw = blockIdx.x * 8 + wid;
  int nwarp = gridDim.x * 8;
  for (int t = gw; t < NT16; t += nwarp) {
    int eb = t * 16;
    if (lane < 16) sS[lane] = eidx[eb + lane];
    else           sD[lane - 16] = eidx[EE + eb + (lane - 16)];
    __syncwarp();
    if (lane < 16) {
      int s = sS[lane], d = sD[lane];
      sRel[lane]      = pos[d*3+0] - pos[s*3+0];
      sRel[16 + lane] = pos[d*3+1] - pos[s*3+1];
      sRel[32 + lane] = pos[d*3+2] - pos[s*3+2];
    }
    __syncwarp();

    float rx0 = sRel[r],     ry0 = sRel[16+r],   rz0 = sRel[32+r];
    float rx1 = sRel[r+8],   ry1 = sRel[16+r+8], rz1 = sRel[32+r+8];
    uint32_t At[4][4];
#pragma unroll
    for (int ks = 0; ks < 4; ks++) {
      float4 wA = sWp1p[16*ks + 2*q];
      float4 wB = sWp1p[16*ks + 2*q + 1];
      float4 wC = sWp1p[16*ks + 2*q + 8];
      float4 wD = sWp1p[16*ks + 2*q + 9];
      float tA0 = fmaxf(fmaf(rx0,wA.x,fmaf(ry0,wA.y,fmaf(rz0,wA.z,wA.w))),0.f);
      float tB0 = fmaxf(fmaf(rx0,wB.x,fmaf(ry0,wB.y,fmaf(rz0,wB.z,wB.w))),0.f);
      float tA1 = fmaxf(fmaf(rx1,wA.x,fmaf(ry1,wA.y,fmaf(rz1,wA.z,wA.w))),0.f);
      float tB1 = fmaxf(fmaf(rx1,wB.x,fmaf(ry1,wB.y,fmaf(rz1,wB.z,wB.w))),0.f);
      float tC0 = fmaxf(fmaf(rx0,wC.x,fmaf(ry0,wC.y,fmaf(rz0,wC.z,wC.w))),0.f);
      float tD0 = fmaxf(fmaf(rx0,wD.x,fmaf(ry0,wD.y,fmaf(rz0,wD.z,wD.w))),0.f);
      float tC1 = fmaxf(fmaf(rx1,wC.x,fmaf(ry1,wC.y,fmaf(rz1,wC.z,wC.w))),0.f);
      float tD1 = fmaxf(fmaf(rx1,wD.x,fmaf(ry1,wD.y,fmaf(rz1,wD.z,wD.w))),0.f);
      At[ks][0] = packbf(tA0, tB0);
      At[ks][1] = packbf(tA1, tB1);
      At[ks][2] = packbf(tC0, tD0);
      At[ks][3] = packbf(tC1, tD1);
    }

    float D1[8][4], D2[8][4];
    wgemm2rb(At, sW12, lane, D1, D2);

#pragma unroll
    for (int h = 0; h < 2; h++) {
#pragma unroll
      for (int s4 = 0; s4 < 4; s4++) {
        int e = s4*4 + eg;
        int dn = sD[e], sn = sS[e];
        int cg = h*32 + c8*4;
        float4 bd = *(const float4*)(g_bdst + dn*64 + cg);
        float4 bs = *(const float4*)(g_bsrc + sn*64 + cg);
        float4 cf = *(const float4*)(scf + cg);
        *(float4*)(scr + e*76 + cg) = make_float4(
            bd.x - bs.x + cf.x, bd.y - bs.y + cf.y,
            bd.z - bs.z + cf.z, bd.w - bs.w + cf.w);
      }
    }
    __syncwarp();

    uint32_t Au[4][4];
#pragma unroll
    for (int ks = 0; ks < 4; ks++) {
      int na = 2*ks, nb = 2*ks + 1;
      float2 g0a = *(const float2*)(scr + r*76 + na*8 + 2*q);
      float2 g1a = *(const float2*)(scr + (r+8)*76 + na*8 + 2*q);
      float2 g0b = *(const float2*)(scr + r*76 + nb*8 + 2*q);
      float2 g1b = *(const float2*)(scr + (r+8)*76 + nb*8 + 2*q);
      Au[ks][0] = packbf(fmaxf(D2[na][0] + g0a.x, 0.f),
                         fmaxf(D2[na][1] + g0a.y, 0.f));
      Au[ks][1] = packbf(fmaxf(D2[na][2] + g1a.x, 0.f),
                         fmaxf(D2[na][3] + g1a.y, 0.f));
      Au[ks][2] = packbf(fmaxf(D2[nb][0] + g0b.x, 0.f),
                         fmaxf(D2[nb][1] + g0b.y, 0.f));
      Au[ks][3] = packbf(fmaxf(D2[nb][2] + g1b.x, 0.f),
                         fmaxf(D2[nb][3] + g1b.y, 0.f));
    }
    __syncwarp();

    float D3[8][4];
    wgemmrb(Au, sW3, lane, D3);

    float* sH1 = scr;
    float* sH3 = scr + 640;
#pragma unroll
    for (int h = 0; h < 2; h++) {
#pragma unroll
      for (int n8l = 0; n8l < 4; n8l++) {
        int n8 = h*4 + n8l;
        *(float2*)(sH1 + r*40 + n8l*8 + 2*q)     = make_float2(D1[n8][0], D1[n8][1]);
        *(float2*)(sH1 + (r+8)*40 + n8l*8 + 2*q) = make_float2(D1[n8][2], D1[n8][3]);
        *(float2*)(sH3 + r*40 + n8l*8 + 2*q)     = make_float2(D3[n8][0], D3[n8][1]);
        *(float2*)(sH3 + (r+8)*40 + n8l*8 + 2*q) = make_float2(D3[n8][2], D3[n8][3]);
      }
      __syncwarp();
#pragma unroll
      for (int s4 = 0; s4 < 4; s4++) {
        int e = s4*4 + eg;
        int dn = sD[e], sn = sS[e];
        int cg = h*32 + c8*4;
        float4 lg = *(const float4*)(sH3 + e*40 + c8*4);
        float4 d1 = *(const float4*)(sH1 + e*40 + c8*4);
        float4 vv = *(const float4*)(g_v + sn*64 + cg);
        float4 ba = *(const float4*)(sba2 + cg);
        float4 bp = *(const float4*)(sbp2 + cg);
        float e0 = __expf(lg.x + ba.x);
        float e1 = __expf(lg.y + ba.y);
        float e2 = __expf(lg.z + ba.z);
        float e3 = __expf(lg.w + ba.w);
        redv4(g_sum + dn*64 + cg, e0, e1, e2, e3);
        redv4(g_num + dn*64 + cg,
              e0 * (vv.x + d1.x + bp.x), e1 * (vv.y + d1.y + bp.y),
              e2 * (vv.z + d1.z + bp.z), e3 * (vv.w + d1.w + bp.w));
      }
      __syncwarp();
    }
  }
}

// ---------------- K3: out = relu((num/(sum+eps))@W_out + b_out), tf32 -------
// smem words: [0,4096) Wout frag-linear; [4096,12800) 8x [16][68] stage; [12800,12864) bout
#define FIN_SM 12864
__global__ void __launch_bounds__(256, 2) k_final(const float* __restrict__ Wout,
                                                  const float* __restrict__ bout,
                                                  float* __restrict__ out) {
  extern __shared__ uint32_t smf[];
  uint32_t* sWf = smf;
  float* sXall  = (float*)(smf + 4096);
  float* sbout  = (float*)(smf + 12800);

  int tid = threadIdx.x;
  int wid = tid >> 5, lane = tid & 31;
  int nb = blockIdx.x * 128 + wid*16;

  stage_tf32(Wout, sWf, tid);
  if (tid < 64) sbout[tid] = bout[tid];
  __syncthreads();

  if (nb >= NN) return;
  float* sX = sXall + wid*1088;

  for (int idx = lane; idx < 256; idx += 32) {
    int row = idx >> 4;
    int c4  = (idx & 15) << 2;
    int n = nb + row;
    float4 v = make_float4(0.f,0.f,0.f,0.f);
    if (n < NN) {
      float4 num = *(const float4*)(g_num + n*64 + c4);
      float4 s   = *(const float4*)(g_sum + n*64 + c4);
      v.x = num.x / (s.x + 1e-16f);
      v.y = num.y / (s.y + 1e-16f);
      v.z = num.z / (s.z + 1e-16f);
      v.w = num.w / (s.w + 1e-16f);
    }
    *(float4*)(sX + row*68 + c4) = v;
  }
  __syncwarp();

  int r = lane >> 2, q = lane & 3;
  uint32_t Ax[8][4];
#pragma unroll
  for (int k8 = 0; k8 < 8; k8++) {
    Ax[k8][0] = f2tf(sX[r*68     + k8*8 + q]);
    Ax[k8][1] = f2tf(sX[(r+8)*68 + k8*8 + q]);
    Ax[k8][2] = f2tf(sX[r*68     + k8*8 + q + 4]);
    Ax[k8][3] = f2tf(sX[(r+8)*68 + k8*8 + q + 4]);
  }

  float D[8][4];
  wgemmr_tf(Ax, sWf, lane, D);

  int ok0 = (nb + r < NN), ok1 = (nb + r + 8 < NN);
#pragma unroll
  for (int n8 = 0; n8 < 8; n8++) {
    int c0 = n8*8 + 2*q, c1 = c0 + 1;
    if (ok0)
      *(float2*)(out + (nb+r)*64 + c0) = make_float2(
          fmaxf(D[n8][0] + sbout[c0], 0.f), fmaxf(D[n8][1] + sbout[c1], 0.f));
    if (ok1)
      *(float2*)(out + (nb+r+8)*64 + c0) = make_float2(
          fmaxf(D[n8][2] + sbout[c0], 0.f), fmaxf(D[n8][3] + sbout[c1], 0.f));
  }
}

// ---------------- launch ----------------
extern "C" void kernel_launch(void* const* d_in, const int* in_sizes, int n_in,
                              void* d_out, int out_size) {
  const float* x    = (const float*)d_in[0];
  const float* pos  = (const float*)d_in[1];
  const int*   eidx = (const int*)  d_in[2];
  const float* W_in = (const float*)d_in[3];
  const float* b_in = (const float*)d_in[4];
  const float* W_lin= (const float*)d_in[5];
  const float* W_src= (const float*)d_in[6];
  const float* W_dst= (const float*)d_in[7];
  const float* Wp1  = (const float*)d_in[8];
  const float* bp1  = (const float*)d_in[9];
  const float* Wp2  = (const float*)d_in[10];
  const float* bp2  = (const float*)d_in[11];
  const float* Wa1  = (const float*)d_in[12];
  const float* ba1  = (const float*)d_in[13];
  const float* Wa2  = (const float*)d_in[14];
  const float* ba2  = (const float*)d_in[15];
  const float* W_out= (const float*)d_in[16];
  const float* b_out= (const float*)d_in[17];
  float* out = (float*)d_out;

  cudaFuncSetAttribute(k_edge, cudaFuncAttributeMaxDynamicSharedMemorySize,
                       SM_WORDS * 4);
  cudaFuncSetAttribute(k_node, cudaFuncAttributeMaxDynamicSharedMemorySize,
                       NODE_SM * 4);
  cudaFuncSetAttribute(k_final, cudaFuncAttributeMaxDynamicSharedMemorySize,
                       FIN_SM * 4);

  kw<<<3, 256>>>(W_src, W_dst, Wp2, Wa1, bp2, ba1);
  k_node<<<(NN + 127) / 128, 256, NODE_SM * 4>>>(x, W_in, b_in, W_lin);
  k_edge<<<296, 256, SM_WORDS * 4>>>(pos, eidx, Wp1, bp1, bp2, Wp2, Wa2, ba2);
  k_final<<<(NN + 127) / 128, 256, FIN_SM * 4>>>(W_out, b_out, out);
}

// round 11
// speedup vs baseline: 4.2600x; 1.1012x over previous
#include <cuda_runtime.h>
#include <math.h>
#include <stdint.h>

#define NN 50000
#define EE 800000
#define CC 64
#define NT16 50000          // EE/16 warp tiles

// -------- device scratch --------
__device__ float g_v[NN*CC];
__device__ float g_bsrc[NN*CC];    // h@(W_src@Wa1)
__device__ float g_bdst[NN*CC];    // h@(W_dst@Wa1)
__device__ float g_sum[NN*CC];     // softmax denominator
__device__ float g_num[NN*CC];     // unnormalized numerator
__device__ float g_Wsa[CC*CC];     // W_src@Wa1
__device__ float g_Wda[CC*CC];     // W_dst@Wa1
__device__ float g_Wfuse[CC*CC];   // Wp2@Wa1
__device__ float g_cfuse[CC];      // bp2@Wa1 + ba1
__device__ uint32_t g_fW[5][4096]; // tf32 frag-linear: Win|Wlin|Wsa|Wda|Wout

// ================= mma.sync helpers =================
__device__ __forceinline__ uint32_t f2tf(float f) {
  uint32_t o;
  asm("cvt.rna.tf32.f32 %0, %1;" : "=r"(o) : "f"(f));
  return o;
}
__device__ __forceinline__ uint32_t packbf(float lo, float hi) {
  uint32_t o;
  asm("cvt.rn.bf16x2.f32 %0, %1, %2;" : "=r"(o) : "f"(hi), "f"(lo));
  return o;
}
__device__ __forceinline__ void mma8(float c[4], uint32_t a0, uint32_t a1,
                                     uint32_t a2, uint32_t a3,
                                     uint32_t b0, uint32_t b1) {
  asm volatile(
      "mma.sync.aligned.m16n8k8.row.col.f32.tf32.tf32.f32 "
      "{%0,%1,%2,%3}, {%4,%5,%6,%7}, {%8,%9}, {%0,%1,%2,%3};"
      : "+f"(c[0]), "+f"(c[1]), "+f"(c[2]), "+f"(c[3])
      : "r"(a0), "r"(a1), "r"(a2), "r"(a3), "r"(b0), "r"(b1));
}
__device__ __forceinline__ void mma16(float c[4], uint32_t a0, uint32_t a1,
                                      uint32_t a2, uint32_t a3,
                                      uint32_t b0, uint32_t b1) {
  asm volatile(
      "mma.sync.aligned.m16n8k16.row.col.f32.bf16.bf16.f32 "
      "{%0,%1,%2,%3}, {%4,%5,%6,%7}, {%8,%9}, {%0,%1,%2,%3};"
      : "+f"(c[0]), "+f"(c[1]), "+f"(c[2]), "+f"(c[3])
      : "r"(a0), "r"(a1), "r"(a2), "r"(a3), "r"(b0), "r"(b1));
}
__device__ __forceinline__ void redv4(float* p, float a, float b, float c, float d) {
  asm volatile("red.global.add.v4.f32 [%0], {%1,%2,%3,%4};"
               :: "l"(p), "f"(a), "f"(b), "f"(c), "f"(d) : "memory");
}

// ---- tf32 warp GEMM, A in regs, B frag-linear (global or shared):
//   frag(k8,n8) at (k8*8+n8)*64 + lane*2
__device__ __forceinline__ void wgemmr_tf(const uint32_t A[8][4],
                                          const uint32_t* __restrict__ B,
                                          int lane, float D[8][4]) {
#pragma unroll
  for (int n8 = 0; n8 < 8; n8++)
#pragma unroll
    for (int j = 0; j < 4; j++) D[n8][j] = 0.f;
#pragma unroll
  for (int k8 = 0; k8 < 8; k8++) {
    const uint32_t* bb = B + (k8<<9) + (lane<<1);
#pragma unroll
    for (int n8 = 0; n8 < 8; n8++) {
      uint2 w = *(const uint2*)(bb + (n8<<6));
      mma8(D[n8], A[k8][0], A[k8][1], A[k8][2], A[k8][3], w.x, w.y);
    }
  }
}

// ---- bf16 dual warp GEMM (B1|B2 interleaved uint4) and single GEMM ----
__device__ __forceinline__ void wgemm2rb(const uint32_t A[4][4],
                                         const uint32_t* __restrict__ sW12,
                                         int lane, float D1[8][4], float D2[8][4]) {
#pragma unroll
  for (int n8 = 0; n8 < 8; n8++)
#pragma unroll
    for (int j = 0; j < 4; j++) { D1[n8][j] = 0.f; D2[n8][j] = 0.f; }
#pragma unroll
  for (int ks = 0; ks < 4; ks++) {
    const uint32_t* b = sW12 + (ks<<10) + (lane<<2);
#pragma unroll
    for (int n8 = 0; n8 < 8; n8++) {
      uint4 w = *(const uint4*)(b + (n8<<7));
      mma16(D1[n8], A[ks][0], A[ks][1], A[ks][2], A[ks][3], w.x, w.y);
      mma16(D2[n8], A[ks][0], A[ks][1], A[ks][2], A[ks][3], w.z, w.w);
    }
  }
}
__device__ __forceinline__ void wgemmrb(const uint32_t A[4][4],
                                        const uint32_t* __restrict__ sB,
                                        int lane, float D[8][4]) {
#pragma unroll
  for (int n8 = 0; n8 < 8; n8++)
#pragma unroll
    for (int j = 0; j < 4; j++) D[n8][j] = 0.f;
#pragma unroll
  for (int ks = 0; ks < 4; ks++) {
    const uint32_t* bb = sB + (ks<<9) + (lane<<1);
#pragma unroll
    for (int n8 = 0; n8 < 8; n8++) {
      uint2 w = *(const uint2*)(bb + (n8<<6));
      mma16(D[n8], A[ks][0], A[ks][1], A[ks][2], A[ks][3], w.x, w.y);
    }
  }
}

// stage fp32 weight matrix [64][64] into tf32 frag-linear layout (4096 words)
__device__ __forceinline__ void stage_tf32(const float* __restrict__ W,
                                           uint32_t* __restrict__ dst, int tid) {
  for (int idx = tid; idx < 4096; idx += 256) {
    int tbit = idx & 1;
    int ln   = (idx & 63) >> 1;
    int kn   = idx >> 6;
    int k8 = kn >> 3, n8 = kn & 7;
    int rr = ln >> 2, qq = ln & 3;
    dst[idx] = f2tf(W[(k8*8 + qq + tbit*4)*64 + n8*8 + rr]);
  }
}

// ---------------- KW: weight-product precompute ----------------
__global__ __launch_bounds__(256) void kw(const float* __restrict__ Wsrc,
    const float* __restrict__ Wdst, const float* __restrict__ Wp2,
    const float* __restrict__ Wa1, const float* __restrict__ bp2,
    const float* __restrict__ ba1) {
  __shared__ float sWa1[4096];
  int tid = threadIdx.x;
#pragma unroll
  for (int t = 0; t < 16; t++) sWa1[t*256 + tid] = Wa1[t*256 + tid];
  __syncthreads();
  const float* A = (blockIdx.x == 0) ? Wsrc : (blockIdx.x == 1) ? Wdst : Wp2;
  float* O = (blockIdx.x == 0) ? g_Wsa : (blockIdx.x == 1) ? g_Wda : g_Wfuse;
  for (int idx = tid; idx < 4096; idx += 256) {
    int k = idx >> 6, n = idx & 63;
    float s = 0.f;
#pragma unroll 16
    for (int m = 0; m < 64; m++) s = fmaf(A[k*64 + m], sWa1[m*64 + n], s);
    O[idx] = s;
  }
  if (blockIdx.x == 2 && tid < 64) {
    float s = ba1[tid];
#pragma unroll 16
    for (int m = 0; m < 64; m++) s = fmaf(bp2[m], sWa1[m*64 + tid], s);
    g_cfuse[tid] = s;
  }
}

// ---------------- KW2: one-time tf32 frag-linear staging ----------------
__global__ __launch_bounds__(256) void kw2(const float* __restrict__ Win,
                                           const float* __restrict__ Wlin,
                                           const float* __restrict__ Wout) {
  int b = blockIdx.x;
  const float* src = (b == 0) ? Win : (b == 1) ? Wlin
                   : (b == 2) ? g_Wsa : (b == 3) ? g_Wda : Wout;
  stage_tf32(src, g_fW[b], threadIdx.x);
}

// ---------------- K1: node projections (tf32 mma, global B-frags) ----------
// 8 warps x 16 nodes per block (128 nodes).
__global__ __launch_bounds__(256, 2) void k_node(const float* __restrict__ x,
                                                 const float* __restrict__ bin) {
  __shared__ float sXall[8*1088];   // 8 x [16][68]
  __shared__ float sbin[64];

  int tid = threadIdx.x;
  int wid = tid >> 5, lane = tid & 31;
  int nb0 = blockIdx.x * 128;

  // zero g_sum/g_num for this node range
#pragma unroll
  for (int j = 0; j < 8; j++) {
    int idx = j*256 + tid;
    int node = nb0 + (idx >> 4);
    int c4 = (idx & 15) << 2;
    if (node < NN) {
      float4 z = make_float4(0.f,0.f,0.f,0.f);
      *(float4*)(g_sum + node*64 + c4) = z;
      *(float4*)(g_num + node*64 + c4) = z;
    }
  }
  if (tid < 64) sbin[tid] = bin[tid];
  __syncthreads();

  int nb = nb0 + wid*16;
  if (nb >= NN) return;
  float* sX = sXall + wid*1088;

  for (int idx = lane; idx < 256; idx += 32) {
    int row = idx >> 4;
    int c4  = (idx & 15) << 2;
    int n = nb + row;
    float4 v = make_float4(0.f,0.f,0.f,0.f);
    if (n < NN) v = *(const float4*)(x + n*64 + c4);
    *(float4*)(sX + row*68 + c4) = v;
  }
  __syncwarp();

  int r = lane >> 2, q = lane & 3;
  int Slo = (lane & ~3) | (q >> 1);
  int Shi = Slo + 2;
  int odd = q & 1;

  uint32_t Ax[8][4];
#pragma unroll
  for (int k8 = 0; k8 < 8; k8++) {
    Ax[k8][0] = f2tf(sX[r*68     + k8*8 + q]);
    Ax[k8][1] = f2tf(sX[(r+8)*68 + k8*8 + q]);
    Ax[k8][2] = f2tf(sX[r*68     + k8*8 + q + 4]);
    Ax[k8][3] = f2tf(sX[(r+8)*68 + k8*8 + q + 4]);
  }

  // GEMM1: h = relu(x@Win + bin), shfl-transpose D->A layout
  float Dh[8][4];
  wgemmr_tf(Ax, g_fW[0], lane, Dh);
  uint32_t Ah[8][4];
#pragma unroll
  for (int n8 = 0; n8 < 8; n8++) {
    int c0 = n8*8 + 2*q, c1 = c0 + 1;
    uint32_t u0 = f2tf(fmaxf(Dh[n8][0] + sbin[c0], 0.f));
    uint32_t u1 = f2tf(fmaxf(Dh[n8][1] + sbin[c1], 0.f));
    uint32_t u2 = f2tf(fmaxf(Dh[n8][2] + sbin[c0], 0.f));
    uint32_t u3 = f2tf(fmaxf(Dh[n8][3] + sbin[c1], 0.f));
    uint32_t v0 = __shfl_sync(0xFFFFFFFFu, u0, Slo);
    uint32_t v1 = __shfl_sync(0xFFFFFFFFu, u1, Slo);
    Ah[n8][0] = odd ? v1 : v0;
    uint32_t v2 = __shfl_sync(0xFFFFFFFFu, u2, Slo);
    uint32_t v3 = __shfl_sync(0xFFFFFFFFu, u3, Slo);
    Ah[n8][1] = odd ? v3 : v2;
    uint32_t w0 = __shfl_sync(0xFFFFFFFFu, u0, Shi);
    uint32_t w1 = __shfl_sync(0xFFFFFFFFu, u1, Shi);
    Ah[n8][2] = odd ? w1 : w0;
    uint32_t w2 = __shfl_sync(0xFFFFFFFFu, u2, Shi);
    uint32_t w3 = __shfl_sync(0xFFFFFFFFu, u3, Shi);
    Ah[n8][3] = odd ? w3 : w2;
  }

  int ok0 = (nb + r < NN), ok1 = (nb + r + 8 < NN);
#pragma unroll
  for (int m = 0; m < 3; m++) {
    float* Om = (m==0) ? g_v : (m==1) ? g_bsrc : g_bdst;
    float D[8][4];
    wgemmr_tf(Ah, g_fW[m+1], lane, D);
#pragma unroll
    for (int n8 = 0; n8 < 8; n8++) {
      int c0 = n8*8 + 2*q;
      if (ok0) *(float2*)(Om + (nb+r)*64 + c0)   = make_float2(D[n8][0], D[n8][1]);
      if (ok1) *(float2*)(Om + (nb+r+8)*64 + c0) = make_float2(D[n8][2], D[n8][3]);
    }
  }
}

// ---------------- K2: fused edge kernel (bf16 m16n8k16) — unchanged --------
#define SM_WORDS 19520
__global__ void __launch_bounds__(256, 2) k_edge(
    const float* __restrict__ pos, const int* __restrict__ eidx,
    const float* __restrict__ Wp1, const float* __restrict__ bp1,
    const float* __restrict__ bp2, const float* __restrict__ Wp2,
    const float* __restrict__ Wa2, const float* __restrict__ ba2) {
  extern __shared__ uint32_t smu[];
  uint32_t* sW12  = smu;                    // 4096
  uint32_t* sW3   = smu + 4096;             // 2048
  float*    sScr  = (float*)(smu + 6144);   // 12288
  float4*   sWp1p = (float4*)(smu + 18432); // 64 float4
  float* sbp2 = (float*)(smu + 18688);
  float* sba2 = (float*)(smu + 18752);
  float* scf  = (float*)(smu + 18816);
  float* sRelAll = (float*)(smu + 18880);
  int*   sIdxAll = (int*)(smu + 19264);

  int tid = threadIdx.x;
  int wid = tid >> 5, lane = tid & 31;

  for (int idx = tid; idx < 2048; idx += 256) {
    int t  = idx & 1;
    int ln = (idx >> 1) & 31;
    int fr = idx >> 6;
    int ks = fr >> 3, n8 = fr & 7;
    int rr = ln >> 2, qq = ln & 3;
    int klo = 16*ks + 2*qq + t*8;
    int col = 8*n8 + rr;
    uint32_t w1 = packbf(Wp2[klo*64 + col],     Wp2[(klo+1)*64 + col]);
    uint32_t w2 = packbf(g_Wfuse[klo*64 + col], g_Wfuse[(klo+1)*64 + col]);
    uint32_t w3 = packbf(Wa2[klo*64 + col],     Wa2[(klo+1)*64 + col]);
    int base12 = (fr << 7) + (ln << 2);
    sW12[base12 + t]     = w1;
    sW12[base12 + 2 + t] = w2;
    sW3[(fr << 6) + (ln << 1) + t] = w3;
  }
  if (tid < 64) {
    sWp1p[tid] = make_float4(Wp1[tid], Wp1[64+tid], Wp1[128+tid], bp1[tid]);
    sbp2[tid] = bp2[tid]; sba2[tid] = ba2[tid]; scf[tid] = g_cfuse[tid];
  }
  __syncthreads();

  float* scr = sScr + wid*1536;
  float* sRel = sRelAll + wid*48;
  int* sS = sIdxAll + wid*32;
  int* sD = sS + 16;

  int r = lane >> 2, q = lane & 3;
  int eg = lane >> 3, c8 = lane & 7;

  int gw = blockIdx.x * 8 + wid;
  int nwarp = gridDim.x * 8;
  for (int t = gw; t < NT16; t += nwarp) {
    int eb = t * 16;
    if (lane < 16) sS[lane] = eidx[eb + lane];
    else           sD[lane - 16] = eidx[EE + eb + (lane - 16)];
    __syncwarp();
    if (lane < 16) {
      int s = sS[lane], d = sD[lane];
      sRel[lane]      = pos[d*3+0] - pos[s*3+0];
      sRel[16 + lane] = pos[d*3+1] - pos[s*3+1];
      sRel[32 + lane] = pos[d*3+2] - pos[s*3+2];
    }
    __syncwarp();

    float rx0 = sRel[r],     ry0 = sRel[16+r],   rz0 = sRel[32+r];
    float rx1 = sRel[r+8],   ry1 = sRel[16+r+8], rz1 = sRel[32+r+8];
    uint32_t At[4][4];
#pragma unroll
    for (int ks = 0; ks < 4; ks++) {
      float4 wA = sWp1p[16*ks + 2*q];
      float4 wB = sWp1p[16*ks + 2*q + 1];
      float4 wC = sWp1p[16*ks + 2*q + 8];
      float4 wD = sWp1p[16*ks + 2*q + 9];
      float tA0 = fmaxf(fmaf(rx0,wA.x,fmaf(ry0,wA.y,fmaf(rz0,wA.z,wA.w))),0.f);
      float tB0 = fmaxf(fmaf(rx0,wB.x,fmaf(ry0,wB.y,fmaf(rz0,wB.z,wB.w))),0.f);
      float tA1 = fmaxf(fmaf(rx1,wA.x,fmaf(ry1,wA.y,fmaf(rz1,wA.z,wA.w))),0.f);
      float tB1 = fmaxf(fmaf(rx1,wB.x,fmaf(ry1,wB.y,fmaf(rz1,wB.z,wB.w))),0.f);
      float tC0 = fmaxf(fmaf(rx0,wC.x,fmaf(ry0,wC.y,fmaf(rz0,wC.z,wC.w))),0.f);
      float tD0 = fmaxf(fmaf(rx0,wD.x,fmaf(ry0,wD.y,fmaf(rz0,wD.z,wD.w))),0.f);
      float tC1 = fmaxf(fmaf(rx1,wC.x,fmaf(ry1,wC.y,fmaf(rz1,wC.z,wC.w))),0.f);
      float tD1 = fmaxf(fmaf(rx1,wD.x,fmaf(ry1,wD.y,fmaf(rz1,wD.z,wD.w))),0.f);
      At[ks][0] = packbf(tA0, tB0);
      At[ks][1] = packbf(tA1, tB1);
      At[ks][2] = packbf(tC0, tD0);
      At[ks][3] = packbf(tC1, tD1);
    }

    float D1[8][4], D2[8][4];
    wgemm2rb(At, sW12, lane, D1, D2);

#pragma unroll
    for (int h = 0; h < 2; h++) {
#pragma unroll
      for (int s4 = 0; s4 < 4; s4++) {
        int e = s4*4 + eg;
        int dn = sD[e], sn = sS[e];
        int cg = h*32 + c8*4;
        float4 bd = *(const float4*)(g_bdst + dn*64 + cg);
        float4 bs = *(const float4*)(g_bsrc + sn*64 + cg);
        float4 cf = *(const float4*)(scf + cg);
        *(float4*)(scr + e*76 + cg) = make_float4(
            bd.x - bs.x + cf.x, bd.y - bs.y + cf.y,
            bd.z - bs.z + cf.z, bd.w - bs.w + cf.w);
      }
    }
    __syncwarp();

    uint32_t Au[4][4];
#pragma unroll
    for (int ks = 0; ks < 4; ks++) {
      int na = 2*ks, nb = 2*ks + 1;
      float2 g0a = *(const float2*)(scr + r*76 + na*8 + 2*q);
      float2 g1a = *(const float2*)(scr + (r+8)*76 + na*8 + 2*q);
      float2 g0b = *(const float2*)(scr + r*76 + nb*8 + 2*q);
      float2 g1b = *(const float2*)(scr + (r+8)*76 + nb*8 + 2*q);
      Au[ks][0] = packbf(fmaxf(D2[na][0] + g0a.x, 0.f),
                         fmaxf(D2[na][1] + g0a.y, 0.f));
      Au[ks][1] = packbf(fmaxf(D2[na][2] + g1a.x, 0.f),
                         fmaxf(D2[na][3] + g1a.y, 0.f));
      Au[ks][2] = packbf(fmaxf(D2[nb][0] + g0b.x, 0.f),
                         fmaxf(D2[nb][1] + g0b.y, 0.f));
      Au[ks][3] = packbf(fmaxf(D2[nb][2] + g1b.x, 0.f),
                         fmaxf(D2[nb][3] + g1b.y, 0.f));
    }
    __syncwarp();

    float D3[8][4];
    wgemmrb(Au, sW3, lane, D3);

    float* sH1 = scr;
    float* sH3 = scr + 640;
#pragma unroll
    for (int h = 0; h < 2; h++) {
#pragma unroll
      for (int n8l = 0; n8l < 4; n8l++) {
        int n8 = h*4 + n8l;
        *(float2*)(sH1 + r*40 + n8l*8 + 2*q)     = make_float2(D1[n8][0], D1[n8][1]);
        *(float2*)(sH1 + (r+8)*40 + n8l*8 + 2*q) = make_float2(D1[n8][2], D1[n8][3]);
        *(float2*)(sH3 + r*40 + n8l*8 + 2*q)     = make_float2(D3[n8][0], D3[n8][1]);
        *(float2*)(sH3 + (r+8)*40 + n8l*8 + 2*q) = make_float2(D3[n8][2], D3[n8][3]);
      }
      __syncwarp();
#pragma unroll
      for (int s4 = 0; s4 < 4; s4++) {
        int e = s4*4 + eg;
        int dn = sD[e], sn = sS[e];
        int cg = h*32 + c8*4;
        float4 lg = *(const float4*)(sH3 + e*40 + c8*4);
        float4 d1 = *(const float4*)(sH1 + e*40 + c8*4);
        float4 vv = *(const float4*)(g_v + sn*64 + cg);
        float4 ba = *(const float4*)(sba2 + cg);
        float4 bp = *(const float4*)(sbp2 + cg);
        float e0 = __expf(lg.x + ba.x);
        float e1 = __expf(lg.y + ba.y);
        float e2 = __expf(lg.z + ba.z);
        float e3 = __expf(lg.w + ba.w);
        redv4(g_sum + dn*64 + cg, e0, e1, e2, e3);
        redv4(g_num + dn*64 + cg,
              e0 * (vv.x + d1.x + bp.x), e1 * (vv.y + d1.y + bp.y),
              e2 * (vv.z + d1.z + bp.z), e3 * (vv.w + d1.w + bp.w));
      }
      __syncwarp();
    }
  }
}

// ---------------- K3: out = relu((num/(sum+eps))@W_out + b_out), tf32 -------
__global__ __launch_bounds__(256, 2) void k_final(const float* __restrict__ bout,
                                                  float* __restrict__ out) {
  __shared__ float sXall[8*1088];
  __shared__ float sbout[64];

  int tid = threadIdx.x;
  int wid = tid >> 5, lane = tid & 31;
  int nb = blockIdx.x * 128 + wid*16;

  if (tid < 64) sbout[tid] = bout[tid];
  __syncthreads();

  if (nb >= NN) return;
  float* sX = sXall + wid*1088;

  for (int idx = lane; idx < 256; idx += 32) {
    int row = idx >> 4;
    int c4  = (idx & 15) << 2;
    int n = nb + row;
    float4 v = make_float4(0.f,0.f,0.f,0.f);
    if (n < NN) {
      float4 num = *(const float4*)(g_num + n*64 + c4);
      float4 s   = *(const float4*)(g_sum + n*64 + c4);
      v.x = num.x / (s.x + 1e-16f);
      v.y = num.y / (s.y + 1e-16f);
      v.z = num.z / (s.z + 1e-16f);
      v.w = num.w / (s.w + 1e-16f);
    }
    *(float4*)(sX + row*68 + c4) = v;
  }
  __syncwarp();

  int r = lane >> 2, q = lane & 3;
  uint32_t Ax[8][4];
#pragma unroll
  for (int k8 = 0; k8 < 8; k8++) {
    Ax[k8][0] = f2tf(sX[r*68     + k8*8 + q]);
    Ax[k8][1] = f2tf(sX[(r+8)*68 + k8*8 + q]);
    Ax[k8][2] = f2tf(sX[r*68     + k8*8 + q + 4]);
    Ax[k8][3] = f2tf(sX[(r+8)*68 + k8*8 + q + 4]);
  }

  float D[8][4];
  wgemmr_tf(Ax, g_fW[4], lane, D);

  int ok0 = (nb + r < NN), ok1 = (nb + r + 8 < NN);
#pragma unroll
  for (int n8 = 0; n8 < 8; n8++) {
    int c0 = n8*8 + 2*q, c1 = c0 + 1;
    if (ok0)
      *(float2*)(out + (nb+r)*64 + c0) = make_float2(
          fmaxf(D[n8][0] + sbout[c0], 0.f), fmaxf(D[n8][1] + sbout[c1], 0.f));
    if (ok1)
      *(float2*)(out + (nb+r+8)*64 + c0) = make_float2(
          fmaxf(D[n8][2] + sbout[c0], 0.f), fmaxf(D[n8][3] + sbout[c1], 0.f));
  }
}

// ---------------- launch ----------------
extern "C" void kernel_launch(void* const* d_in, const int* in_sizes, int n_in,
                              void* d_out, int out_size) {
  const float* x    = (const float*)d_in[0];
  const float* pos  = (const float*)d_in[1];
  const int*   eidx = (const int*)  d_in[2];
  const float* W_in = (const float*)d_in[3];
  const float* b_in = (const float*)d_in[4];
  const float* W_lin= (const float*)d_in[5];
  const float* W_src= (const float*)d_in[6];
  const float* W_dst= (const float*)d_in[7];
  const float* Wp1  = (const float*)d_in[8];
  const float* bp1  = (const float*)d_in[9];
  const float* Wp2  = (const float*)d_in[10];
  const float* bp2  = (const float*)d_in[11];
  const float* Wa1  = (const float*)d_in[12];
  const float* ba1  = (const float*)d_in[13];
  const float* Wa2  = (const float*)d_in[14];
  const float* ba2  = (const float*)d_in[15];
  const float* W_out= (const float*)d_in[16];
  const float* b_out= (const float*)d_in[17];
  float* out = (float*)d_out;

  cudaFuncSetAttribute(k_edge, cudaFuncAttributeMaxDynamicSharedMemorySize,
                       SM_WORDS * 4);

  kw<<<3, 256>>>(W_src, W_dst, Wp2, Wa1, bp2, ba1);
  kw2<<<5, 256>>>(W_in, W_lin, W_out);
  k_node<<<(NN + 127) / 128, 256>>>(x, b_in);
  k_edge<<<296, 256, SM_WORDS * 4>>>(pos, eidx, Wp1, bp1, bp2, Wp2, Wa2, ba2);
  k_final<<<(NN + 127) / 128, 256>>>(b_out, out);
}